// round 2
// baseline (speedup 1.0000x reference)
#include <cuda_runtime.h>

#define B_   8
#define N_   2048
#define K_   32
#define D_   64
#define C1_  64
#define C2_  128
#define BN_  (B_*N_)
#define R2_  0.0225f
#define EPS_ 1e-5f
#define CNT_ 524288.0   /* B*N*K */

// ---------------- device scratch (no dynamic allocation allowed) ----------------
__device__ int    g_idx[BN_*K_];        // 2 MB   ball-query indices
__device__ float  g_F1[BN_*C1_];        // 4 MB   feature @ W1[3:,:]  (L2 resident)
__device__ double g_sum1[C1_], g_sq1[C1_];
__device__ double g_sum2[C2_], g_sq2[C2_];
__device__ float  g_a1[C1_], g_b1[C1_]; // BN1 as y = a*x + b
__device__ float  g_a2[C2_], g_b2[C2_];
__device__ float  g_mx[BN_*C2_];        // 8 MB  per-(point,ch) max of pre-BN h2
__device__ float  g_mn[BN_*C2_];        // 8 MB  per-(point,ch) min

// ---------------- 0) zero stats ----------------
__global__ void k_zero() {
    int t = threadIdx.x;
    if (t < C1_) { g_sum1[t] = 0.0; g_sq1[t] = 0.0; }
    if (t < C2_) { g_sum2[t] = 0.0; g_sq2[t] = 0.0; }
}

// ---------------- 1) ball query ----------------
// One warp per query point. Positions + norms of the whole batch in smem.
// Collect first 32 indices (ascending) with sq <= r^2; pad with first.
__global__ void k_ball(const float* __restrict__ pos) {
    __shared__ float sx[N_], sy[N_], sz[N_], sn[N_];
    __shared__ int   sbuf[8][K_];
    int b    = blockIdx.x / (N_ / 8);
    int qblk = blockIdx.x % (N_ / 8);
    const float* p = pos + (size_t)b * N_ * 3;
    for (int i = threadIdx.x; i < N_; i += blockDim.x) {
        float x = p[3*i], y = p[3*i+1], z = p[3*i+2];
        sx[i] = x; sy[i] = y; sz[i] = z; sn[i] = x*x + y*y + z*z;
    }
    __syncthreads();

    int w = threadIdx.x >> 5, lane = threadIdx.x & 31;
    int q = qblk * 8 + w;
    float qx = sx[q], qy = sy[q], qz = sz[q], qn = sn[q];
    int* buf = sbuf[w];
    int cnt = 0;
    for (int base = 0; base < N_ && cnt < K_; base += 32) {
        int m = base + lane;
        float dot = qx*sx[m] + qy*sy[m] + qz*sz[m];
        float sq  = qn + sn[m] - 2.0f*dot;
        bool in   = (sq <= R2_);
        unsigned mask = __ballot_sync(0xffffffffu, in);
        if (in) {
            int pslot = cnt + __popc(mask & ((1u << lane) - 1u));
            if (pslot < K_) buf[pslot] = m;
        }
        cnt += __popc(mask);
    }
    __syncwarp();
    // self is always within radius -> cnt >= 1, buf[0] valid
    int v = (lane < cnt) ? buf[lane] : buf[0];
    g_idx[(b*N_ + q)*K_ + lane] = v;
}

// ---------------- 2) F1 = feature @ W1[3:,:]  (16384 x 64 @ 64 x 64) ----------------
__global__ void k_f1(const float* __restrict__ feat, const float* __restrict__ W1) {
    __shared__ float sW[D_][C1_];     // 16 KB
    __shared__ float sIn[32][D_+1];   // padded
    int row0 = blockIdx.x * 32;
    for (int i = threadIdx.x; i < D_*C1_; i += 256)
        sW[i / C1_][i % C1_] = W1[(3 + i / C1_) * C1_ + (i % C1_)];
    for (int i = threadIdx.x; i < 32*D_; i += 256)
        sIn[i / D_][i % D_] = feat[(size_t)(row0 + i / D_) * D_ + (i % D_)];
    __syncthreads();
    int k = threadIdx.x >> 3, c0 = (threadIdx.x & 7) << 3;
    float acc[8];
#pragma unroll
    for (int j = 0; j < 8; j++) acc[j] = 0.f;
    for (int i = 0; i < D_; i++) {
        float a = sIn[k][i];
#pragma unroll
        for (int j = 0; j < 8; j++) acc[j] = fmaf(a, sW[i][c0 + j], acc[j]);
    }
#pragma unroll
    for (int j = 0; j < 8; j++)
        g_F1[(size_t)(row0 + k) * C1_ + c0 + j] = acc[j];
}

// ---------------- 3) stats of h1 (pre-BN), h1 recomputed, never stored ----------------
__global__ void k_stats1(const float* __restrict__ pos, const float* __restrict__ W1) {
    __shared__ float ssum[C1_], ssq[C1_];
    __shared__ float sWx[3*C1_];
    int t = threadIdx.x;
    if (t < C1_) { ssum[t] = 0.f; ssq[t] = 0.f; }
    if (t < 3*C1_) sWx[t] = W1[t];
    __syncthreads();

    int k = t >> 3, c0 = (t & 7) << 3;
    float ls[8], lq[8];
#pragma unroll
    for (int j = 0; j < 8; j++) { ls[j] = 0.f; lq[j] = 0.f; }

    int bn0 = blockIdx.x * 8;
    for (int g = 0; g < 8; g++) {
        int bn = bn0 + g;
        int b  = bn >> 11;                 // / N_
        int m  = g_idx[bn*K_ + k];
        float cx = pos[bn*3+0], cy = pos[bn*3+1], cz = pos[bn*3+2];
        const float* pm = pos + (size_t)(b*N_ + m) * 3;
        float dx = pm[0]-cx, dy = pm[1]-cy, dz = pm[2]-cz;
        const float* f1 = g_F1 + (size_t)(b*N_ + m) * C1_ + c0;
#pragma unroll
        for (int j = 0; j < 8; j++) {
            int c = c0 + j;
            float v = f1[j] + dx*sWx[c] + dy*sWx[C1_+c] + dz*sWx[2*C1_+c];
            ls[j] += v; lq[j] = fmaf(v, v, lq[j]);
        }
    }
#pragma unroll
    for (int j = 0; j < 8; j++) {
        atomicAdd(&ssum[c0+j], ls[j]);
        atomicAdd(&ssq [c0+j], lq[j]);
    }
    __syncthreads();
    if (t < C1_) {
        atomicAdd(&g_sum1[t], (double)ssum[t]);
        atomicAdd(&g_sq1 [t], (double)ssq [t]);
    }
}

// ---------------- 4) BN1 coefficients ----------------
__global__ void k_bn1(const float* __restrict__ gamma, const float* __restrict__ beta) {
    int t = threadIdx.x;
    if (t < C1_) {
        double mean = g_sum1[t] / CNT_;
        double var  = g_sq1[t] / CNT_ - mean * mean;
        float a = rsqrtf((float)var + EPS_) * gamma[t];
        g_a1[t] = a;
        g_b1[t] = beta[t] - (float)mean * a;
    }
}

// ---------------- 5) main pass: recompute h1, BN1+ReLU, @W2, track max/min + stats2 ----------------
// 4 groups (= 128 rows) per block, 8x8 register tiles, 256 threads.
#define G2_ROWS 128
#define G2_SMEM (( (D_*C2_) + (G2_ROWS*65) + (16*C2_)*2 + 3*C1_ + 2*C1_ + 4*G2_ROWS + 2*C2_ ) * 4)

extern __shared__ float dynsmem[];
__global__ __launch_bounds__(256, 2)
void k_gemm2(const float* __restrict__ pos, const float* __restrict__ W1,
             const float* __restrict__ W2) {
    float* sW   = dynsmem;                 // 64*128
    float* sH   = sW  + D_*C2_;            // 128*65 (padded)
    float* sMx  = sH  + G2_ROWS*65;        // 16*128 partial max per row-block
    float* sMn  = sMx + 16*C2_;            // 16*128
    float* sWx  = sMn + 16*C2_;            // 3*64
    float* sA   = sWx + 3*C1_;             // 64
    float* sB   = sA  + C1_;               // 64
    float* sDx  = sB  + C1_;               // 128
    float* sDy  = sDx + G2_ROWS;
    float* sDz  = sDy + G2_ROWS;
    int*   sM   = (int*)(sDz + G2_ROWS);   // 128
    float* ssum = (float*)(sM + G2_ROWS);  // 128
    float* ssq  = ssum + C2_;              // 128

    int t   = threadIdx.x;
    int bn0 = blockIdx.x * 4;

    for (int i = t; i < D_*C2_; i += 256) sW[i] = W2[i];
    if (t < 3*C1_) sWx[t] = W1[t];
    if (t < C1_)   { sA[t] = g_a1[t]; sB[t] = g_b1[t]; }
    if (t < C2_)   { ssum[t] = 0.f; ssq[t] = 0.f; }
    if (t < G2_ROWS) {
        int r  = t;
        int bn = bn0 + (r >> 5);
        int k  = r & 31;
        int b  = bn >> 11;
        int m  = g_idx[bn*K_ + k];
        sM[r]  = b*N_ + m;
        float cx = pos[bn*3+0], cy = pos[bn*3+1], cz = pos[bn*3+2];
        const float* pm = pos + (size_t)(b*N_ + m) * 3;
        sDx[r] = pm[0]-cx; sDy[r] = pm[1]-cy; sDz[r] = pm[2]-cz;
    }
    __syncthreads();

    // build h1n = relu(a1 * h1 + b1) in smem
    for (int i = t; i < G2_ROWS*D_; i += 256) {
        int r = i >> 6, c = i & 63;
        float v = g_F1[(size_t)sM[r]*C1_ + c]
                + sDx[r]*sWx[c] + sDy[r]*sWx[C1_+c] + sDz[r]*sWx[2*C1_+c];
        v = fmaf(v, sA[c], sB[c]);
        sH[r*65 + c] = fmaxf(v, 0.f);
    }
    __syncthreads();

    // 128x64 @ 64x128 with 8x8 tiles
    int r0 = (t >> 4) * 8;
    int c0 = (t & 15) * 8;
    float acc[8][8];
#pragma unroll
    for (int r = 0; r < 8; r++)
#pragma unroll
        for (int j = 0; j < 8; j++) acc[r][j] = 0.f;

    for (int i = 0; i < D_; i++) {
        float fa[8];
#pragma unroll
        for (int r = 0; r < 8; r++) fa[r] = sH[(r0 + r)*65 + i];
        float4 b0 = *(const float4*)(sW + i*C2_ + c0);
        float4 b1 = *(const float4*)(sW + i*C2_ + c0 + 4);
        float fb[8] = {b0.x, b0.y, b0.z, b0.w, b1.x, b1.y, b1.z, b1.w};
#pragma unroll
        for (int r = 0; r < 8; r++)
#pragma unroll
            for (int j = 0; j < 8; j++)
                acc[r][j] = fmaf(fa[r], fb[j], acc[r][j]);
    }

    // per-thread reductions: max/min over 8 rows (same group), stats partials
    int rblk = t >> 4;
#pragma unroll
    for (int j = 0; j < 8; j++) {
        float mx = acc[0][j], mn = acc[0][j], s = 0.f, q = 0.f;
#pragma unroll
        for (int r = 0; r < 8; r++) {
            float v = acc[r][j];
            mx = fmaxf(mx, v); mn = fminf(mn, v);
            s += v; q = fmaf(v, v, q);
        }
        sMx[rblk*C2_ + c0 + j] = mx;
        sMn[rblk*C2_ + c0 + j] = mn;
        atomicAdd(&ssum[c0+j], s);
        atomicAdd(&ssq [c0+j], q);
    }
    __syncthreads();

    // reduce 4 row-blocks per group, write max/min to global
    for (int i = t; i < 4*C2_; i += 256) {
        int grp = i >> 7, c = i & 127;
        int rb0 = grp * 4;
        float mx = sMx[rb0*C2_ + c];
        float mn = sMn[rb0*C2_ + c];
#pragma unroll
        for (int rb = 1; rb < 4; rb++) {
            mx = fmaxf(mx, sMx[(rb0+rb)*C2_ + c]);
            mn = fminf(mn, sMn[(rb0+rb)*C2_ + c]);
        }
        g_mx[(size_t)(bn0 + grp)*C2_ + c] = mx;
        g_mn[(size_t)(bn0 + grp)*C2_ + c] = mn;
    }
    if (t < C2_) {
        atomicAdd(&g_sum2[t], (double)ssum[t]);
        atomicAdd(&g_sq2 [t], (double)ssq [t]);
    }
}

// ---------------- 6) BN2 coefficients ----------------
__global__ void k_bn2(const float* __restrict__ gamma, const float* __restrict__ beta) {
    int t = threadIdx.x;
    if (t < C2_) {
        double mean = g_sum2[t] / CNT_;
        double var  = g_sq2[t] / CNT_ - mean * mean;
        float a = rsqrtf((float)var + EPS_) * gamma[t];
        g_a2[t] = a;
        g_b2[t] = beta[t] - (float)mean * a;
    }
}

// ---------------- 7) epilogue: relu(bn2(max-or-min)) ----------------
// monotone a>=0 -> max commutes; a<0 -> use min.
__global__ void k_out(float* __restrict__ out) {
    int i = blockIdx.x * blockDim.x + threadIdx.x;
    if (i >= BN_*C2_) return;
    int c = i & (C2_ - 1);
    float a = g_a2[c], b = g_b2[c];
    float x = (a >= 0.f) ? g_mx[i] : g_mn[i];
    out[i] = fmaxf(fmaf(a, x, b), 0.f);
}

// ---------------- launch ----------------
extern "C" void kernel_launch(void* const* d_in, const int* in_sizes, int n_in,
                              void* d_out, int out_size) {
    const float* pos    = (const float*)d_in[0];
    const float* feat   = (const float*)d_in[1];
    const float* W1     = (const float*)d_in[2];
    const float* gamma1 = (const float*)d_in[3];
    const float* beta1  = (const float*)d_in[4];
    const float* W2     = (const float*)d_in[5];
    const float* gamma2 = (const float*)d_in[6];
    const float* beta2  = (const float*)d_in[7];
    float* out = (float*)d_out;

    cudaFuncSetAttribute(k_gemm2, cudaFuncAttributeMaxDynamicSharedMemorySize, G2_SMEM);

    k_zero  <<<1, 256>>>();
    k_ball  <<<B_*(N_/8), 256>>>(pos);
    k_f1    <<<BN_/32, 256>>>(feat, W1);
    k_stats1<<<BN_/8, 256>>>(pos, W1);
    k_bn1   <<<1, 64>>>(gamma1, beta1);
    k_gemm2 <<<BN_/4, 256, G2_SMEM>>>(pos, W1, W2);
    k_bn2   <<<1, 128>>>(gamma2, beta2);
    k_out   <<<(BN_*C2_ + 255)/256, 256>>>(out + BN_*3);
    cudaMemcpyAsync(out, pos, (size_t)BN_*3*sizeof(float),
                    cudaMemcpyDeviceToDevice);
}

// round 3
// speedup vs baseline: 1.1601x; 1.1601x over previous
#include <cuda_runtime.h>

#define B_   8
#define N_   2048
#define K_   32
#define D_   64
#define C1_  64
#define C2_  128
#define BN_  (B_*N_)
#define R2_  0.0225f
#define EPS_ 1e-5f
#define CNT_ 524288.0   /* B*N*K */

typedef unsigned long long ull;

// packed fp32x2 helpers (FFMA2 path — ptxas never emits this from C++)
__device__ __forceinline__ void fma2(ull& d, ull a, ull b) {
    asm("fma.rn.f32x2 %0, %1, %2, %0;" : "+l"(d) : "l"(a), "l"(b));
}
__device__ __forceinline__ ull pack2(float x, float y) {
    ull r; asm("mov.b64 %0, {%1, %2};" : "=l"(r) : "f"(x), "f"(y)); return r;
}
__device__ __forceinline__ void unpack2(float& x, float& y, ull v) {
    asm("mov.b64 {%0, %1}, %2;" : "=f"(x), "=f"(y) : "l"(v));
}

// ---------------- device scratch ----------------
__device__ int    g_idx[BN_*K_];
__device__ float  g_F1[BN_*C1_];        // feature @ W1[3:,:]  (4 MB, L2 resident)
__device__ double g_sum1[C1_], g_sq1[C1_];
__device__ double g_sum2[C2_], g_sq2[C2_];
__device__ float  g_a1[C1_], g_b1[C1_];
__device__ float  g_a2[C2_], g_b2[C2_];
__device__ float  g_mx[BN_*C2_];
__device__ float  g_mn[BN_*C2_];

// ---------------- 0) zero stats ----------------
__global__ void k_zero() {
    int t = threadIdx.x;
    if (t < C1_) { g_sum1[t] = 0.0; g_sq1[t] = 0.0; }
    if (t < C2_) { g_sum2[t] = 0.0; g_sq2[t] = 0.0; }
}

// ---------------- 1) ball query: 8 warps x 4 queries per block ----------------
__global__ void k_ball(const float* __restrict__ pos) {
    __shared__ float sx[N_], sy[N_], sz[N_], sn[N_];
    __shared__ int   sbuf[8][K_];
    int b    = blockIdx.x >> 6;            // 64 blocks per batch
    int qblk = blockIdx.x & 63;            // 32 queries per block
    const float* p = pos + (size_t)b * N_ * 3;
    for (int i = threadIdx.x; i < N_; i += blockDim.x) {
        float x = p[3*i], y = p[3*i+1], z = p[3*i+2];
        sx[i] = x; sy[i] = y; sz[i] = z; sn[i] = x*x + y*y + z*z;
    }
    __syncthreads();

    int w = threadIdx.x >> 5, lane = threadIdx.x & 31;
    int* buf = sbuf[w];
    for (int qq = 0; qq < 4; qq++) {
        int q = qblk * 32 + w * 4 + qq;
        float qx = sx[q], qy = sy[q], qz = sz[q], qn = sn[q];
        int cnt = 0;
        for (int base = 0; base < N_ && cnt < K_; base += 32) {
            int m = base + lane;
            float dot = qx*sx[m] + qy*sy[m] + qz*sz[m];
            float sq  = qn + sn[m] - 2.0f*dot;
            bool in   = (sq <= R2_);
            unsigned mask = __ballot_sync(0xffffffffu, in);
            if (in) {
                int pslot = cnt + __popc(mask & ((1u << lane) - 1u));
                if (pslot < K_) buf[pslot] = m;
            }
            cnt += __popc(mask);
        }
        __syncwarp();
        int v = (lane < cnt) ? buf[lane] : buf[0];
        g_idx[(b*N_ + q)*K_ + lane] = v;
        __syncwarp();
    }
}

// ---------------- 2) F1 = feature @ W1[3:,:] ----------------
__global__ void k_f1(const float* __restrict__ feat, const float* __restrict__ W1) {
    __shared__ float sW[D_][C1_];
    __shared__ float sIn[32][D_+1];
    int row0 = blockIdx.x * 32;
    for (int i = threadIdx.x; i < D_*C1_; i += 256)
        sW[i / C1_][i % C1_] = W1[(3 + i / C1_) * C1_ + (i % C1_)];
    for (int i = threadIdx.x; i < 32*D_; i += 256)
        sIn[i / D_][i % D_] = feat[(size_t)(row0 + i / D_) * D_ + (i % D_)];
    __syncthreads();
    int k = threadIdx.x >> 3, c0 = (threadIdx.x & 7) << 3;
    ull acc[4];
#pragma unroll
    for (int j = 0; j < 4; j++) acc[j] = 0ull;
    for (int i = 0; i < D_; i++) {
        ull a = pack2(sIn[k][i], sIn[k][i]);
        const ull* wr = (const ull*)&sW[i][c0];
#pragma unroll
        for (int j = 0; j < 4; j++) fma2(acc[j], a, wr[j]);
    }
    float* o = &g_F1[(size_t)(row0 + k) * C1_ + c0];
#pragma unroll
    for (int j = 0; j < 4; j++) { float x, y; unpack2(x, y, acc[j]); o[2*j] = x; o[2*j+1] = y; }
}

// ---------------- 3) stats of h1: coalesced gather, warp-per-query ----------------
// 512 blocks x 8 warps x 4 queries. Lane owns channels (2*lane, 2*lane+1).
__global__ void k_stats1(const float* __restrict__ pos, const float* __restrict__ W1) {
    __shared__ float sx[N_], sy[N_], sz[N_];
    __shared__ float ssum[C1_], ssq[C1_];
    int t = threadIdx.x;
    int b    = blockIdx.x >> 6;
    int qblk = blockIdx.x & 63;
    const float* p = pos + (size_t)b * N_ * 3;
    for (int i = t; i < N_; i += 256) {
        sx[i] = p[3*i]; sy[i] = p[3*i+1]; sz[i] = p[3*i+2];
    }
    if (t < C1_) { ssum[t] = 0.f; ssq[t] = 0.f; }
    __syncthreads();

    int w = t >> 5, lane = t & 31;
    float wx0 = W1[2*lane],     wx1 = W1[2*lane+1];
    float wy0 = W1[C1_+2*lane], wy1 = W1[C1_+2*lane+1];
    float wz0 = W1[2*C1_+2*lane], wz1 = W1[2*C1_+2*lane+1];

    float s0 = 0.f, s1 = 0.f, q0 = 0.f, q1 = 0.f;
    const float* F1b = g_F1 + (size_t)b * N_ * C1_;
    for (int qq = 0; qq < 4; qq++) {
        int ql = qblk * 32 + w * 4 + qq;
        int mk = g_idx[((size_t)b*N_ + ql)*K_ + lane];
        float cx = sx[ql], cy = sy[ql], cz = sz[ql];
#pragma unroll 8
        for (int k = 0; k < K_; k++) {
            int m = __shfl_sync(0xffffffffu, mk, k);
            float dx = sx[m] - cx, dy = sy[m] - cy, dz = sz[m] - cz;
            float2 f = *(const float2*)(F1b + (size_t)m * C1_ + 2*lane);
            float v0 = f.x + dx*wx0 + dy*wy0 + dz*wz0;
            float v1 = f.y + dx*wx1 + dy*wy1 + dz*wz1;
            s0 += v0; q0 = fmaf(v0, v0, q0);
            s1 += v1; q1 = fmaf(v1, v1, q1);
        }
    }
    atomicAdd(&ssum[2*lane],   s0);
    atomicAdd(&ssum[2*lane+1], s1);
    atomicAdd(&ssq [2*lane],   q0);
    atomicAdd(&ssq [2*lane+1], q1);
    __syncthreads();
    if (t < C1_) {
        atomicAdd(&g_sum1[t], (double)ssum[t]);
        atomicAdd(&g_sq1 [t], (double)ssq [t]);
    }
}

// ---------------- 4) BN1 coefficients ----------------
__global__ void k_bn1(const float* __restrict__ gamma, const float* __restrict__ beta) {
    int t = threadIdx.x;
    if (t < C1_) {
        double mean = g_sum1[t] / CNT_;
        double var  = g_sq1[t] / CNT_ - mean * mean;
        float a = rsqrtf((float)var + EPS_) * gamma[t];
        g_a1[t] = a;
        g_b1[t] = beta[t] - (float)mean * a;
    }
}

// ---------------- 5) main pass: h1 -> BN1+ReLU -> @W2 (FFMA2), max/min + stats2 ----------------
#define G2_ROWS 128
#define G2_SMEM (( (D_*C2_) + (G2_ROWS*65) + (16*C2_)*2 + 3*C1_ + 2*C1_ + 4*G2_ROWS + 2*C2_ ) * 4)

extern __shared__ float dynsmem[];
__global__ __launch_bounds__(256, 2)
void k_gemm2(const float* __restrict__ pos, const float* __restrict__ W1,
             const float* __restrict__ W2) {
    float* sW   = dynsmem;                 // 64*128
    float* sH   = sW  + D_*C2_;            // 128*65
    float* sMx  = sH  + G2_ROWS*65;        // 16*128
    float* sMn  = sMx + 16*C2_;            // 16*128
    float* sWx  = sMn + 16*C2_;            // 3*64
    float* sA   = sWx + 3*C1_;             // 64
    float* sB   = sA  + C1_;               // 64
    float* sDx  = sB  + C1_;               // 128
    float* sDy  = sDx + G2_ROWS;
    float* sDz  = sDy + G2_ROWS;
    int*   sM   = (int*)(sDz + G2_ROWS);   // 128
    float* ssum = (float*)(sM + G2_ROWS);  // 128
    float* ssq  = ssum + C2_;              // 128

    int t   = threadIdx.x;
    int bn0 = blockIdx.x * 4;

    for (int i = t; i < D_*C2_; i += 256) sW[i] = W2[i];
    if (t < 3*C1_) sWx[t] = W1[t];
    if (t < C1_)   { sA[t] = g_a1[t]; sB[t] = g_b1[t]; }
    if (t < C2_)   { ssum[t] = 0.f; ssq[t] = 0.f; }
    if (t < G2_ROWS) {
        int r  = t;
        int bn = bn0 + (r >> 5);
        int k  = r & 31;
        int b  = bn >> 11;
        int m  = g_idx[bn*K_ + k];
        sM[r]  = b*N_ + m;
        float cx = pos[bn*3+0], cy = pos[bn*3+1], cz = pos[bn*3+2];
        const float* pm = pos + (size_t)(b*N_ + m) * 3;
        sDx[r] = pm[0]-cx; sDy[r] = pm[1]-cy; sDz[r] = pm[2]-cz;
    }
    __syncthreads();

    // build h1n = relu(a1 * h1 + b1) in smem (coalesced F1 reads)
    for (int i = t; i < G2_ROWS*D_; i += 256) {
        int r = i >> 6, c = i & 63;
        float v = g_F1[(size_t)sM[r]*C1_ + c]
                + sDx[r]*sWx[c] + sDy[r]*sWx[C1_+c] + sDz[r]*sWx[2*C1_+c];
        v = fmaf(v, sA[c], sB[c]);
        sH[r*65 + c] = fmaxf(v, 0.f);
    }
    __syncthreads();

    // 128x64 @ 64x128 with 8x8 tiles, packed f32x2 FMA
    int r0 = (t >> 4) * 8;
    int c0 = (t & 15) * 8;
    ull acc[8][4];
#pragma unroll
    for (int r = 0; r < 8; r++)
#pragma unroll
        for (int j = 0; j < 4; j++) acc[r][j] = 0ull;

    for (int i = 0; i < D_; i++) {
        const ull* wr = (const ull*)(sW + i*C2_ + c0);
        ull fb[4];
#pragma unroll
        for (int j = 0; j < 4; j++) fb[j] = wr[j];
#pragma unroll
        for (int r = 0; r < 8; r++) {
            float a = sH[(r0 + r)*65 + i];
            ull ap = pack2(a, a);
#pragma unroll
            for (int j = 0; j < 4; j++) fma2(acc[r][j], ap, fb[j]);
        }
    }

    // per-thread reductions over 8 rows; stats partials
    int rblk = t >> 4;
#pragma unroll
    for (int j = 0; j < 4; j++) {
        float v0[8], v1[8];
#pragma unroll
        for (int r = 0; r < 8; r++) unpack2(v0[r], v1[r], acc[r][j]);
#pragma unroll
        for (int half = 0; half < 2; half++) {
            float* vv = half ? v1 : v0;
            int c = c0 + 2*j + half;
            float mx = vv[0], mn = vv[0], s = 0.f, q = 0.f;
#pragma unroll
            for (int r = 0; r < 8; r++) {
                float v = vv[r];
                mx = fmaxf(mx, v); mn = fminf(mn, v);
                s += v; q = fmaf(v, v, q);
            }
            sMx[rblk*C2_ + c] = mx;
            sMn[rblk*C2_ + c] = mn;
            atomicAdd(&ssum[c], s);
            atomicAdd(&ssq [c], q);
        }
    }
    __syncthreads();

    for (int i = t; i < 4*C2_; i += 256) {
        int grp = i >> 7, c = i & 127;
        int rb0 = grp * 4;
        float mx = sMx[rb0*C2_ + c];
        float mn = sMn[rb0*C2_ + c];
#pragma unroll
        for (int rb = 1; rb < 4; rb++) {
            mx = fmaxf(mx, sMx[(rb0+rb)*C2_ + c]);
            mn = fminf(mn, sMn[(rb0+rb)*C2_ + c]);
        }
        g_mx[(size_t)(bn0 + grp)*C2_ + c] = mx;
        g_mn[(size_t)(bn0 + grp)*C2_ + c] = mn;
    }
    if (t < C2_) {
        atomicAdd(&g_sum2[t], (double)ssum[t]);
        atomicAdd(&g_sq2 [t], (double)ssq [t]);
    }
}

// ---------------- 6) BN2 coefficients ----------------
__global__ void k_bn2(const float* __restrict__ gamma, const float* __restrict__ beta) {
    int t = threadIdx.x;
    if (t < C2_) {
        double mean = g_sum2[t] / CNT_;
        double var  = g_sq2[t] / CNT_ - mean * mean;
        float a = rsqrtf((float)var + EPS_) * gamma[t];
        g_a2[t] = a;
        g_b2[t] = beta[t] - (float)mean * a;
    }
}

// ---------------- 7) epilogue ----------------
__global__ void k_out(float* __restrict__ out) {
    int i = blockIdx.x * blockDim.x + threadIdx.x;
    if (i >= BN_*C2_) return;
    int c = i & (C2_ - 1);
    float a = g_a2[c], b = g_b2[c];
    float x = (a >= 0.f) ? g_mx[i] : g_mn[i];
    out[i] = fmaxf(fmaf(a, x, b), 0.f);
}

// ---------------- launch ----------------
extern "C" void kernel_launch(void* const* d_in, const int* in_sizes, int n_in,
                              void* d_out, int out_size) {
    const float* pos    = (const float*)d_in[0];
    const float* feat   = (const float*)d_in[1];
    const float* W1     = (const float*)d_in[2];
    const float* gamma1 = (const float*)d_in[3];
    const float* beta1  = (const float*)d_in[4];
    const float* W2     = (const float*)d_in[5];
    const float* gamma2 = (const float*)d_in[6];
    const float* beta2  = (const float*)d_in[7];
    float* out = (float*)d_out;

    cudaFuncSetAttribute(k_gemm2, cudaFuncAttributeMaxDynamicSharedMemorySize, G2_SMEM);

    k_zero  <<<1, 256>>>();
    k_ball  <<<B_*(N_/32), 256>>>(pos);
    k_f1    <<<BN_/32, 256>>>(feat, W1);
    k_stats1<<<B_*(N_/32), 256>>>(pos, W1);
    k_bn1   <<<1, 64>>>(gamma1, beta1);
    k_gemm2 <<<BN_/4, 256, G2_SMEM>>>(pos, W1, W2);
    k_bn2   <<<1, 128>>>(gamma2, beta2);
    k_out   <<<(BN_*C2_ + 255)/256, 256>>>(out + BN_*3);
    cudaMemcpyAsync(out, pos, (size_t)BN_*3*sizeof(float),
                    cudaMemcpyDeviceToDevice);
}

// round 5
// speedup vs baseline: 1.7055x; 1.4702x over previous
#include <cuda_runtime.h>
#include <cuda_bf16.h>
#include <cstdint>

#define B_   8
#define N_   2048
#define K_   32
#define D_   64
#define C1_  64
#define C2_  128
#define BN_  (B_*N_)
#define R2_  0.0225f
#define EPS_ 1e-5f
#define CNT_ 524288.0   /* B*N*K */

typedef unsigned long long ull;

// ---------------- helpers ----------------
__device__ __forceinline__ uint32_t smem_u32(const void* p) {
    uint32_t a;
    asm("{ .reg .u64 t; cvta.to.shared.u64 t, %1; cvt.u32.u64 %0, t; }" : "=r"(a) : "l"(p));
    return a;
}
#define SW128(off) ((off) ^ (((off) >> 3) & 0x70))

// m16n8k16 bf16 MMA, f32 accumulate (baseline PTX, sm_80+ -> HMMA on sm_103)
__device__ __forceinline__ void mma_bf16(float* d, const uint32_t* a, const uint32_t* b) {
    asm volatile(
        "mma.sync.aligned.m16n8k16.row.col.f32.bf16.bf16.f32 "
        "{%0,%1,%2,%3}, {%4,%5,%6,%7}, {%8,%9}, {%0,%1,%2,%3};"
        : "+f"(d[0]), "+f"(d[1]), "+f"(d[2]), "+f"(d[3])
        : "r"(a[0]), "r"(a[1]), "r"(a[2]), "r"(a[3]), "r"(b[0]), "r"(b[1]));
}
__device__ __forceinline__ void ldsm_x4(uint32_t* r, uint32_t addr) {
    asm volatile("ldmatrix.sync.aligned.m8n8.x4.shared.b16 {%0,%1,%2,%3}, [%4];"
        : "=r"(r[0]), "=r"(r[1]), "=r"(r[2]), "=r"(r[3]) : "r"(addr));
}

// packed fp32x2 helpers (k_f1)
__device__ __forceinline__ void fma2(ull& d, ull a, ull b) {
    asm("fma.rn.f32x2 %0, %1, %2, %0;" : "+l"(d) : "l"(a), "l"(b));
}
__device__ __forceinline__ ull pack2(float x, float y) {
    ull r; asm("mov.b64 %0, {%1, %2};" : "=l"(r) : "f"(x), "f"(y)); return r;
}
__device__ __forceinline__ void unpack2(float& x, float& y, ull v) {
    asm("mov.b64 {%0, %1}, %2;" : "=f"(x), "=f"(y) : "l"(v));
}

// ---------------- device scratch ----------------
__device__ int    g_idx[BN_*K_];
__device__ float  g_F1[BN_*C1_];
__device__ double g_sum1[C1_], g_sq1[C1_];
__device__ double g_sum2[C2_], g_sq2[C2_];
__device__ float  g_a1[C1_], g_b1[C1_];
__device__ float  g_a2[C2_], g_b2[C2_];
__device__ float  g_mx[BN_*C2_];
__device__ float  g_mn[BN_*C2_];
__device__ __nv_bfloat16 g_W2t_hi[C2_*D_];   // [n][k] transposed split of W2
__device__ __nv_bfloat16 g_W2t_lo[C2_*D_];

// ---------------- 0) zero stats ----------------
__global__ void k_zero() {
    int t = threadIdx.x;
    if (t < C1_) { g_sum1[t] = 0.0; g_sq1[t] = 0.0; }
    if (t < C2_) { g_sum2[t] = 0.0; g_sq2[t] = 0.0; }
}

// ---------------- 1) ball query ----------------
__global__ void k_ball(const float* __restrict__ pos) {
    __shared__ float sx[N_], sy[N_], sz[N_], sn[N_];
    __shared__ int   sbuf[8][K_];
    int b    = blockIdx.x >> 6;
    int qblk = blockIdx.x & 63;
    const float* p = pos + (size_t)b * N_ * 3;
    for (int i = threadIdx.x; i < N_; i += blockDim.x) {
        float x = p[3*i], y = p[3*i+1], z = p[3*i+2];
        sx[i] = x; sy[i] = y; sz[i] = z; sn[i] = x*x + y*y + z*z;
    }
    __syncthreads();
    int w = threadIdx.x >> 5, lane = threadIdx.x & 31;
    int* buf = sbuf[w];
    for (int qq = 0; qq < 4; qq++) {
        int q = qblk * 32 + w * 4 + qq;
        float qx = sx[q], qy = sy[q], qz = sz[q], qn = sn[q];
        int cnt = 0;
        for (int base = 0; base < N_ && cnt < K_; base += 32) {
            int m = base + lane;
            float dot = qx*sx[m] + qy*sy[m] + qz*sz[m];
            float sq  = qn + sn[m] - 2.0f*dot;
            bool in   = (sq <= R2_);
            unsigned mask = __ballot_sync(0xffffffffu, in);
            if (in) {
                int pslot = cnt + __popc(mask & ((1u << lane) - 1u));
                if (pslot < K_) buf[pslot] = m;
            }
            cnt += __popc(mask);
        }
        __syncwarp();
        int v = (lane < cnt) ? buf[lane] : buf[0];
        g_idx[(b*N_ + q)*K_ + lane] = v;
        __syncwarp();
    }
}

// ---------------- 2) F1 = feature @ W1[3:,:] ----------------
__global__ void k_f1(const float* __restrict__ feat, const float* __restrict__ W1) {
    __shared__ float sW[D_][C1_];
    __shared__ float sIn[32][D_+1];
    int row0 = blockIdx.x * 32;
    for (int i = threadIdx.x; i < D_*C1_; i += 256)
        sW[i / C1_][i % C1_] = W1[(3 + i / C1_) * C1_ + (i % C1_)];
    for (int i = threadIdx.x; i < 32*D_; i += 256)
        sIn[i / D_][i % D_] = feat[(size_t)(row0 + i / D_) * D_ + (i % D_)];
    __syncthreads();
    int k = threadIdx.x >> 3, c0 = (threadIdx.x & 7) << 3;
    ull acc[4];
#pragma unroll
    for (int j = 0; j < 4; j++) acc[j] = 0ull;
    for (int i = 0; i < D_; i++) {
        ull a = pack2(sIn[k][i], sIn[k][i]);
        const ull* wr = (const ull*)&sW[i][c0];
#pragma unroll
        for (int j = 0; j < 4; j++) fma2(acc[j], a, wr[j]);
    }
    float* o = &g_F1[(size_t)(row0 + k) * C1_ + c0];
#pragma unroll
    for (int j = 0; j < 4; j++) { float x, y; unpack2(x, y, acc[j]); o[2*j] = x; o[2*j+1] = y; }
}

// ---------------- 2b) split-transpose W2 into bf16 hi/lo ----------------
__global__ void k_wsplit(const float* __restrict__ W2) {
    int i = blockIdx.x * 256 + threadIdx.x;
    if (i >= D_*C2_) return;
    int k = i >> 7, n = i & 127;
    float v = W2[i];
    __nv_bfloat16 hi = __float2bfloat16(v);
    __nv_bfloat16 lo = __float2bfloat16(v - __bfloat162float(hi));
    g_W2t_hi[n*D_ + k] = hi;
    g_W2t_lo[n*D_ + k] = lo;
}

// ---------------- 3) stats of h1 ----------------
__global__ void k_stats1(const float* __restrict__ pos, const float* __restrict__ W1) {
    __shared__ float sx[N_], sy[N_], sz[N_];
    __shared__ float ssum[C1_], ssq[C1_];
    int t = threadIdx.x;
    int b    = blockIdx.x >> 6;
    int qblk = blockIdx.x & 63;
    const float* p = pos + (size_t)b * N_ * 3;
    for (int i = t; i < N_; i += 256) {
        sx[i] = p[3*i]; sy[i] = p[3*i+1]; sz[i] = p[3*i+2];
    }
    if (t < C1_) { ssum[t] = 0.f; ssq[t] = 0.f; }
    __syncthreads();

    int w = t >> 5, lane = t & 31;
    float wx0 = W1[2*lane],       wx1 = W1[2*lane+1];
    float wy0 = W1[C1_+2*lane],   wy1 = W1[C1_+2*lane+1];
    float wz0 = W1[2*C1_+2*lane], wz1 = W1[2*C1_+2*lane+1];

    float s0 = 0.f, s1 = 0.f, q0 = 0.f, q1 = 0.f;
    const float* F1b = g_F1 + (size_t)b * N_ * C1_;
    for (int qq = 0; qq < 4; qq++) {
        int ql = qblk * 32 + w * 4 + qq;
        int mk = g_idx[((size_t)b*N_ + ql)*K_ + lane];
        float cx = sx[ql], cy = sy[ql], cz = sz[ql];
#pragma unroll 8
        for (int k = 0; k < K_; k++) {
            int m = __shfl_sync(0xffffffffu, mk, k);
            float dx = sx[m] - cx, dy = sy[m] - cy, dz = sz[m] - cz;
            float2 f = *(const float2*)(F1b + (size_t)m * C1_ + 2*lane);
            float v0 = f.x + dx*wx0 + dy*wy0 + dz*wz0;
            float v1 = f.y + dx*wx1 + dy*wy1 + dz*wz1;
            s0 += v0; q0 = fmaf(v0, v0, q0);
            s1 += v1; q1 = fmaf(v1, v1, q1);
        }
    }
    atomicAdd(&ssum[2*lane],   s0);
    atomicAdd(&ssum[2*lane+1], s1);
    atomicAdd(&ssq [2*lane],   q0);
    atomicAdd(&ssq [2*lane+1], q1);
    __syncthreads();
    if (t < C1_) {
        atomicAdd(&g_sum1[t], (double)ssum[t]);
        atomicAdd(&g_sq1 [t], (double)ssq [t]);
    }
}

// ---------------- 4) BN1 coefficients ----------------
__global__ void k_bn1(const float* __restrict__ gamma, const float* __restrict__ beta) {
    int t = threadIdx.x;
    if (t < C1_) {
        double mean = g_sum1[t] / CNT_;
        double var  = g_sq1[t] / CNT_ - mean * mean;
        float a = rsqrtf((float)var + EPS_) * gamma[t];
        g_a1[t] = a;
        g_b1[t] = beta[t] - (float)mean * a;
    }
}

// ---------------- 5) HMMA gemm2: h1 -> BN1+ReLU -> split bf16 -> mma.sync -> warp reduce ----------------
// smem (1024-aligned base):
//   [    0,16384) A_hi  128x64 bf16, 128B rows, SW128
//   [16384,32768) A_lo
//   [32768,49152) B_hi  128n x 64k bf16 ([n][k]), SW128
//   [49152,65536) B_lo
//   [65536,...)   extras
#define OFF_ALO  16384
#define OFF_BHI  32768
#define OFF_BLO  49152
#define OFF_EX   65536
#define G2T_SMEM (OFF_EX + 1088*4 + 1024)

extern __shared__ char dynraw[];
__global__ __launch_bounds__(256, 2)
void k_gemm2t(const float* __restrict__ pos, const float* __restrict__ W1) {
    uint32_t rawb  = smem_u32(dynraw);
    uint32_t abase = (rawb + 1023) & ~1023u;
    char*    al    = dynraw + (abase - rawb);
    float*   ex    = (float*)(al + OFF_EX);

    float* sWx  = ex;          // 192
    float* sA1  = ex + 192;    // 64
    float* sB1  = ex + 256;    // 64
    float* sDx  = ex + 320;    // 128
    float* sDy  = ex + 448;
    float* sDz  = ex + 576;
    int*   sM   = (int*)(ex + 704);   // 128
    float* ssum = ex + 832;    // 128
    float* ssq  = ex + 960;    // 128

    int t   = threadIdx.x;
    int wid = t >> 5, lane = t & 31;
    int bn0 = blockIdx.x * 4;

    if (t < 3*C1_) sWx[t] = W1[t];
    if (t < C1_)   { sA1[t] = g_a1[t]; sB1[t] = g_b1[t]; }
    if (t < C2_)   { ssum[t] = 0.f; ssq[t] = 0.f; }
    if (t < 128) {
        int r  = t;
        int bn = bn0 + (r >> 5);
        int k  = r & 31;
        int b  = bn >> 11;
        int m  = g_idx[bn*K_ + k];
        sM[r]  = b*N_ + m;
        float cx = pos[bn*3+0], cy = pos[bn*3+1], cz = pos[bn*3+2];
        const float* pm = pos + (size_t)(b*N_ + m) * 3;
        sDx[r] = pm[0]-cx; sDy[r] = pm[1]-cy; sDz[r] = pm[2]-cz;
    }

    // B tiles (8B chunks survive SW128: only 16B-chunk position bits are XORed)
    for (int i = t; i < 128*16; i += 256) {
        int n = i >> 4, k8 = i & 15;
        uint32_t off = SW128((uint32_t)(n*128 + k8*8));
        *(ull*)(al + OFF_BHI + off) = ((const ull*)g_W2t_hi)[i];
        *(ull*)(al + OFF_BLO + off) = ((const ull*)g_W2t_lo)[i];
    }
    __syncthreads();

    // A tiles: h1n = relu(a1*h1+b1), split into bf16 hi/lo pairs
    for (int i = t; i < 128*32; i += 256) {
        int r = i >> 5, c = (i & 31) * 2;
        float2 f = *(const float2*)(g_F1 + (size_t)sM[r]*C1_ + c);
        float dx = sDx[r], dy = sDy[r], dz = sDz[r];
        float v0 = f.x + dx*sWx[c]   + dy*sWx[C1_+c]   + dz*sWx[2*C1_+c];
        float v1 = f.y + dx*sWx[c+1] + dy*sWx[C1_+c+1] + dz*sWx[2*C1_+c+1];
        v0 = fmaxf(fmaf(v0, sA1[c],   sB1[c]),   0.f);
        v1 = fmaxf(fmaf(v1, sA1[c+1], sB1[c+1]), 0.f);
        __nv_bfloat16 h0 = __float2bfloat16(v0);
        __nv_bfloat16 h1 = __float2bfloat16(v1);
        __nv_bfloat16 l0 = __float2bfloat16(v0 - __bfloat162float(h0));
        __nv_bfloat16 l1 = __float2bfloat16(v1 - __bfloat162float(h1));
        uint32_t hp = (uint32_t)*(const uint16_t*)&h0 | ((uint32_t)*(const uint16_t*)&h1 << 16);
        uint32_t lp = (uint32_t)*(const uint16_t*)&l0 | ((uint32_t)*(const uint16_t*)&l1 << 16);
        uint32_t off = SW128((uint32_t)(r*128 + c*2));
        *(uint32_t*)(al + off)           = hp;
        *(uint32_t*)(al + OFF_ALO + off) = lp;
    }
    __syncthreads();

    // warp tiling: 4 row-warps x 2 col-warps; warp tile = 32 rows (one query) x 64 cols
    int w_r = wid & 3, w_c = wid >> 2;
    uint32_t Ah = abase, Al = abase + OFF_ALO;
    uint32_t Bh = abase + OFF_BHI, Bl = abase + OFF_BLO;

    int rowA = w_r*32 + (lane & 15);
    int kbA  = (lane >> 4) * 16;
    int nB   = w_c*64 + ((lane >> 4) << 3) + (lane & 7);
    int kbB  = ((lane >> 3) & 1) * 16;

    float acc[2][8][4];
#pragma unroll
    for (int mt = 0; mt < 2; mt++)
#pragma unroll
        for (int nt = 0; nt < 8; nt++)
#pragma unroll
            for (int j = 0; j < 4; j++) acc[mt][nt][j] = 0.f;

#pragma unroll
    for (int ks = 0; ks < 4; ks++) {
        uint32_t oA[2], oB[4];
#pragma unroll
        for (int mt = 0; mt < 2; mt++)
            oA[mt] = SW128((uint32_t)((rowA + mt*16)*128 + ks*32 + kbA));
#pragma unroll
        for (int np = 0; np < 4; np++)
            oB[np] = SW128((uint32_t)((nB + np*16)*128 + ks*32 + kbB));

        uint32_t af[2][4], bf[4][4];
        // split 0: Ahi * Bhi
#pragma unroll
        for (int mt = 0; mt < 2; mt++) ldsm_x4(af[mt], Ah + oA[mt]);
#pragma unroll
        for (int np = 0; np < 4; np++) ldsm_x4(bf[np], Bh + oB[np]);
#pragma unroll
        for (int mt = 0; mt < 2; mt++)
#pragma unroll
            for (int nt = 0; nt < 8; nt++)
                mma_bf16(acc[mt][nt], af[mt], &bf[nt >> 1][(nt & 1) * 2]);
        // split 1: Ahi * Blo
#pragma unroll
        for (int np = 0; np < 4; np++) ldsm_x4(bf[np], Bl + oB[np]);
#pragma unroll
        for (int mt = 0; mt < 2; mt++)
#pragma unroll
            for (int nt = 0; nt < 8; nt++)
                mma_bf16(acc[mt][nt], af[mt], &bf[nt >> 1][(nt & 1) * 2]);
        // split 2: Alo * Bhi
#pragma unroll
        for (int mt = 0; mt < 2; mt++) ldsm_x4(af[mt], Al + oA[mt]);
#pragma unroll
        for (int np = 0; np < 4; np++) ldsm_x4(bf[np], Bh + oB[np]);
#pragma unroll
        for (int mt = 0; mt < 2; mt++)
#pragma unroll
            for (int nt = 0; nt < 8; nt++)
                mma_bf16(acc[mt][nt], af[mt], &bf[nt >> 1][(nt & 1) * 2]);
    }

    // epilogue: reduce each column over the warp's 32 rows (one query)
    int bnq = bn0 + w_r;
#pragma unroll
    for (int nt = 0; nt < 8; nt++) {
        float a0 = acc[0][nt][0], a2 = acc[0][nt][2], c0v = acc[1][nt][0], c2v = acc[1][nt][2];
        float a1 = acc[0][nt][1], a3 = acc[0][nt][3], c1v = acc[1][nt][1], c3v = acc[1][nt][3];
        float mx0 = fmaxf(fmaxf(a0, a2), fmaxf(c0v, c2v));
        float mn0 = fminf(fminf(a0, a2), fminf(c0v, c2v));
        float s0  = (a0 + a2) + (c0v + c2v);
        float q0  = fmaf(a0,a0, fmaf(a2,a2, fmaf(c0v,c0v, c2v*c2v)));
        float mx1 = fmaxf(fmaxf(a1, a3), fmaxf(c1v, c3v));
        float mn1 = fminf(fminf(a1, a3), fminf(c1v, c3v));
        float s1  = (a1 + a3) + (c1v + c3v);
        float q1  = fmaf(a1,a1, fmaf(a3,a3, fmaf(c1v,c1v, c3v*c3v)));
#pragma unroll
        for (int m = 4; m < 32; m <<= 1) {
            mx0 = fmaxf(mx0, __shfl_xor_sync(0xffffffffu, mx0, m));
            mn0 = fminf(mn0, __shfl_xor_sync(0xffffffffu, mn0, m));
            s0 += __shfl_xor_sync(0xffffffffu, s0, m);
            q0 += __shfl_xor_sync(0xffffffffu, q0, m);
            mx1 = fmaxf(mx1, __shfl_xor_sync(0xffffffffu, mx1, m));
            mn1 = fminf(mn1, __shfl_xor_sync(0xffffffffu, mn1, m));
            s1 += __shfl_xor_sync(0xffffffffu, s1, m);
            q1 += __shfl_xor_sync(0xffffffffu, q1, m);
        }
        if (lane < 4) {
            int c = w_c*64 + nt*8 + 2*lane;
            *(float2*)&g_mx[(size_t)bnq*C2_ + c] = make_float2(mx0, mx1);
            *(float2*)&g_mn[(size_t)bnq*C2_ + c] = make_float2(mn0, mn1);
            atomicAdd(&ssum[c],   s0);
            atomicAdd(&ssum[c+1], s1);
            atomicAdd(&ssq [c],   q0);
            atomicAdd(&ssq [c+1], q1);
        }
    }
    __syncthreads();
    if (t < C2_) {
        atomicAdd(&g_sum2[t], (double)ssum[t]);
        atomicAdd(&g_sq2 [t], (double)ssq [t]);
    }
}

// ---------------- 6) BN2 coefficients ----------------
__global__ void k_bn2(const float* __restrict__ gamma, const float* __restrict__ beta) {
    int t = threadIdx.x;
    if (t < C2_) {
        double mean = g_sum2[t] / CNT_;
        double var  = g_sq2[t] / CNT_ - mean * mean;
        float a = rsqrtf((float)var + EPS_) * gamma[t];
        g_a2[t] = a;
        g_b2[t] = beta[t] - (float)mean * a;
    }
}

// ---------------- 7) epilogue ----------------
__global__ void k_out(float* __restrict__ out) {
    int i = blockIdx.x * blockDim.x + threadIdx.x;
    if (i >= BN_*C2_) return;
    int c = i & (C2_ - 1);
    float a = g_a2[c], b = g_b2[c];
    float x = (a >= 0.f) ? g_mx[i] : g_mn[i];
    out[i] = fmaxf(fmaf(a, x, b), 0.f);
}

// ---------------- launch ----------------
extern "C" void kernel_launch(void* const* d_in, const int* in_sizes, int n_in,
                              void* d_out, int out_size) {
    const float* pos    = (const float*)d_in[0];
    const float* feat   = (const float*)d_in[1];
    const float* W1     = (const float*)d_in[2];
    const float* gamma1 = (const float*)d_in[3];
    const float* beta1  = (const float*)d_in[4];
    const float* W2     = (const float*)d_in[5];
    const float* gamma2 = (const float*)d_in[6];
    const float* beta2  = (const float*)d_in[7];
    float* out = (float*)d_out;

    cudaFuncSetAttribute(k_gemm2t, cudaFuncAttributeMaxDynamicSharedMemorySize, G2T_SMEM);

    k_zero   <<<1, 256>>>();
    k_ball   <<<B_*(N_/32), 256>>>(pos);
    k_f1     <<<BN_/32, 256>>>(feat, W1);
    k_wsplit <<<(D_*C2_ + 255)/256, 256>>>(W2);
    k_stats1 <<<B_*(N_/32), 256>>>(pos, W1);
    k_bn1    <<<1, 64>>>(gamma1, beta1);
    k_gemm2t <<<BN_/4, 256, G2T_SMEM>>>(pos, W1);
    k_bn2    <<<1, 128>>>(gamma2, beta2);
    k_out    <<<(BN_*C2_ + 255)/256, 256>>>(out + BN_*3);
    cudaMemcpyAsync(out, pos, (size_t)BN_*3*sizeof(float),
                    cudaMemcpyDeviceToDevice);
}

// round 6
// speedup vs baseline: 1.7664x; 1.0357x over previous
#include <cuda_runtime.h>
#include <cuda_bf16.h>
#include <cstdint>

#define B_   8
#define N_   2048
#define K_   32
#define D_   64
#define C1_  64
#define C2_  128
#define BN_  (B_*N_)
#define R2_  0.0225f
#define EPS_ 1e-5f
#define RCNT_ (1.0/524288.0)   /* exact: 2^-19 */

typedef unsigned long long ull;

// ---------------- helpers ----------------
__device__ __forceinline__ uint32_t smem_u32(const void* p) {
    uint32_t a;
    asm("{ .reg .u64 t; cvta.to.shared.u64 t, %1; cvt.u32.u64 %0, t; }" : "=r"(a) : "l"(p));
    return a;
}
#define SW128(off) ((off) ^ (((off) >> 3) & 0x70))

__device__ __forceinline__ void mma_bf16(float* d, const uint32_t* a, const uint32_t* b) {
    asm volatile(
        "mma.sync.aligned.m16n8k16.row.col.f32.bf16.bf16.f32 "
        "{%0,%1,%2,%3}, {%4,%5,%6,%7}, {%8,%9}, {%0,%1,%2,%3};"
        : "+f"(d[0]), "+f"(d[1]), "+f"(d[2]), "+f"(d[3])
        : "r"(a[0]), "r"(a[1]), "r"(a[2]), "r"(a[3]), "r"(b[0]), "r"(b[1]));
}
__device__ __forceinline__ void ldsm_x4(uint32_t* r, uint32_t addr) {
    asm volatile("ldmatrix.sync.aligned.m8n8.x4.shared.b16 {%0,%1,%2,%3}, [%4];"
        : "=r"(r[0]), "=r"(r[1]), "=r"(r[2]), "=r"(r[3]) : "r"(addr));
}

// packed fp32x2 helpers (k_f1)
__device__ __forceinline__ void fma2(ull& d, ull a, ull b) {
    asm("fma.rn.f32x2 %0, %1, %2, %0;" : "+l"(d) : "l"(a), "l"(b));
}
__device__ __forceinline__ ull pack2(float x, float y) {
    ull r; asm("mov.b64 %0, {%1, %2};" : "=l"(r) : "f"(x), "f"(y)); return r;
}
__device__ __forceinline__ void unpack2(float& x, float& y, ull v) {
    asm("mov.b64 {%0, %1}, %2;" : "=f"(x), "=f"(y) : "l"(v));
}

// ---------------- device scratch ----------------
__device__ int    g_idx[BN_*K_];
__device__ float  g_F1[BN_*C1_];
__device__ double g_sum1[C1_], g_sq1[C1_];
__device__ double g_sum2[C2_], g_sq2[C2_];
__device__ float  g_mx[BN_*C2_];
__device__ float  g_mn[BN_*C2_];
__device__ __nv_bfloat16 g_W2t_hi[C2_*D_];
__device__ __nv_bfloat16 g_W2t_lo[C2_*D_];

// ---------------- 0) init: zero stats + split-transpose W2 ----------------
__global__ void k_init(const float* __restrict__ W2) {
    int t = threadIdx.x;
    if (blockIdx.x == 0) {
        if (t < C1_) { g_sum1[t] = 0.0; g_sq1[t] = 0.0; }
        if (t < C2_) { g_sum2[t] = 0.0; g_sq2[t] = 0.0; }
    }
    int i = blockIdx.x * 256 + t;
    if (i < D_*C2_) {
        int k = i >> 7, n = i & 127;
        float v = W2[i];
        __nv_bfloat16 hi = __float2bfloat16(v);
        __nv_bfloat16 lo = __float2bfloat16(v - __bfloat162float(hi));
        g_W2t_hi[n*D_ + k] = hi;
        g_W2t_lo[n*D_ + k] = lo;
    }
}

// ---------------- 1) F1 = feature @ W1[3:,:] ----------------
__global__ void k_f1(const float* __restrict__ feat, const float* __restrict__ W1) {
    __shared__ float sW[D_][C1_];
    __shared__ float sIn[32][D_+1];
    int row0 = blockIdx.x * 32;
    for (int i = threadIdx.x; i < D_*C1_; i += 256)
        sW[i / C1_][i % C1_] = W1[(3 + i / C1_) * C1_ + (i % C1_)];
    for (int i = threadIdx.x; i < 32*D_; i += 256)
        sIn[i / D_][i % D_] = feat[(size_t)(row0 + i / D_) * D_ + (i % D_)];
    __syncthreads();
    int k = threadIdx.x >> 3, c0 = (threadIdx.x & 7) << 3;
    ull acc[4];
#pragma unroll
    for (int j = 0; j < 4; j++) acc[j] = 0ull;
    for (int i = 0; i < D_; i++) {
        ull a = pack2(sIn[k][i], sIn[k][i]);
        const ull* wr = (const ull*)&sW[i][c0];
#pragma unroll
        for (int j = 0; j < 4; j++) fma2(acc[j], a, wr[j]);
    }
    float* o = &g_F1[(size_t)(row0 + k) * C1_ + c0];
#pragma unroll
    for (int j = 0; j < 4; j++) { float x, y; unpack2(x, y, acc[j]); o[2*j] = x; o[2*j+1] = y; }
}

// ---------------- 2) fused ball query + h1 stats ----------------
// 512 blocks: (batch b, 32 queries). One position-tile load serves both phases.
__global__ void k_ballstats(const float* __restrict__ pos, const float* __restrict__ W1) {
    __shared__ float sx[N_], sy[N_], sz[N_], sn[N_];
    __shared__ int   sbuf[8][K_];
    __shared__ float ssum[C1_], ssq[C1_];
    int t = threadIdx.x;
    int b    = blockIdx.x >> 6;
    int qblk = blockIdx.x & 63;
    const float* p = pos + (size_t)b * N_ * 3;
    for (int i = t; i < N_; i += 256) {
        float x = p[3*i], y = p[3*i+1], z = p[3*i+2];
        sx[i] = x; sy[i] = y; sz[i] = z; sn[i] = x*x + y*y + z*z;
    }
    if (t < C1_) { ssum[t] = 0.f; ssq[t] = 0.f; }
    __syncthreads();

    int w = t >> 5, lane = t & 31;
    int* buf = sbuf[w];
    // per-lane channel pair weights for the stats phase
    float wx0 = W1[2*lane],       wx1 = W1[2*lane+1];
    float wy0 = W1[C1_+2*lane],   wy1 = W1[C1_+2*lane+1];
    float wz0 = W1[2*C1_+2*lane], wz1 = W1[2*C1_+2*lane+1];
    const float* F1b = g_F1 + (size_t)b * N_ * C1_;

    float s0 = 0.f, s1 = 0.f, q0 = 0.f, q1 = 0.f;
    for (int qq = 0; qq < 4; qq++) {
        int q = qblk * 32 + w * 4 + qq;
        float qx = sx[q], qy = sy[q], qz = sz[q], qn = sn[q];
        int cnt = 0;
        for (int base = 0; base < N_ && cnt < K_; base += 32) {
            int m = base + lane;
            float dot = qx*sx[m] + qy*sy[m] + qz*sz[m];
            float sq  = qn + sn[m] - 2.0f*dot;
            bool in   = (sq <= R2_);
            unsigned mask = __ballot_sync(0xffffffffu, in);
            if (in) {
                int pslot = cnt + __popc(mask & ((1u << lane) - 1u));
                if (pslot < K_) buf[pslot] = m;
            }
            cnt += __popc(mask);
        }
        __syncwarp();
        int v = (lane < cnt) ? buf[lane] : buf[0];
        g_idx[(b*N_ + q)*K_ + lane] = v;
        __syncwarp();

        // stats phase for this query, idx still in-register
#pragma unroll 8
        for (int k = 0; k < K_; k++) {
            int m = __shfl_sync(0xffffffffu, v, k);
            float dx = sx[m] - qx, dy = sy[m] - qy, dz = sz[m] - qz;
            float2 f = *(const float2*)(F1b + (size_t)m * C1_ + 2*lane);
            float v0 = f.x + dx*wx0 + dy*wy0 + dz*wz0;
            float v1 = f.y + dx*wx1 + dy*wy1 + dz*wz1;
            s0 += v0; q0 = fmaf(v0, v0, q0);
            s1 += v1; q1 = fmaf(v1, v1, q1);
        }
    }
    atomicAdd(&ssum[2*lane],   s0);
    atomicAdd(&ssum[2*lane+1], s1);
    atomicAdd(&ssq [2*lane],   q0);
    atomicAdd(&ssq [2*lane+1], q1);
    __syncthreads();
    if (t < C1_) {
        atomicAdd(&g_sum1[t], (double)ssum[t]);
        atomicAdd(&g_sq1 [t], (double)ssq [t]);
    }
}

// ---------------- 3) HMMA gemm2 (BN1 coefficients computed inline) ----------------
#define OFF_ALO  16384
#define OFF_BHI  32768
#define OFF_BLO  49152
#define OFF_EX   65536
#define G2T_SMEM (OFF_EX + 1088*4 + 1024)

extern __shared__ char dynraw[];
__global__ __launch_bounds__(256, 2)
void k_gemm2t(const float* __restrict__ pos, const float* __restrict__ W1,
              const float* __restrict__ gamma1, const float* __restrict__ beta1) {
    uint32_t rawb  = smem_u32(dynraw);
    uint32_t abase = (rawb + 1023) & ~1023u;
    char*    al    = dynraw + (abase - rawb);
    float*   ex    = (float*)(al + OFF_EX);

    float* sWx  = ex;          // 192
    float* sA1  = ex + 192;    // 64
    float* sB1  = ex + 256;    // 64
    float* sDx  = ex + 320;    // 128
    float* sDy  = ex + 448;
    float* sDz  = ex + 576;
    int*   sM   = (int*)(ex + 704);   // 128
    float* ssum = ex + 832;    // 128
    float* ssq  = ex + 960;    // 128

    int t   = threadIdx.x;
    int wid = t >> 5, lane = t & 31;
    int bn0 = blockIdx.x * 4;

    if (t < 3*C1_) sWx[t] = W1[t];
    if (t < C1_) {
        // BN1 coefficients inline (2^-19 multiply is exact; matches separate kernel bit-for-bit)
        double mean = g_sum1[t] * RCNT_;
        double var  = g_sq1[t] * RCNT_ - mean * mean;
        float a = rsqrtf((float)var + EPS_) * gamma1[t];
        sA1[t] = a;
        sB1[t] = beta1[t] - (float)mean * a;
    }
    if (t < C2_)   { ssum[t] = 0.f; ssq[t] = 0.f; }
    if (t < 128) {
        int r  = t;
        int bn = bn0 + (r >> 5);
        int k  = r & 31;
        int b  = bn >> 11;
        int m  = g_idx[bn*K_ + k];
        sM[r]  = b*N_ + m;
        float cx = pos[bn*3+0], cy = pos[bn*3+1], cz = pos[bn*3+2];
        const float* pm = pos + (size_t)(b*N_ + m) * 3;
        sDx[r] = pm[0]-cx; sDy[r] = pm[1]-cy; sDz[r] = pm[2]-cz;
    }

    // B tiles (8B chunks survive SW128)
    for (int i = t; i < 128*16; i += 256) {
        int n = i >> 4, k8 = i & 15;
        uint32_t off = SW128((uint32_t)(n*128 + k8*8));
        *(ull*)(al + OFF_BHI + off) = ((const ull*)g_W2t_hi)[i];
        *(ull*)(al + OFF_BLO + off) = ((const ull*)g_W2t_lo)[i];
    }
    __syncthreads();

    // A tiles: h1n = relu(a1*h1+b1), split to bf16 hi/lo
    for (int i = t; i < 128*32; i += 256) {
        int r = i >> 5, c = (i & 31) * 2;
        float2 f = *(const float2*)(g_F1 + (size_t)sM[r]*C1_ + c);
        float dx = sDx[r], dy = sDy[r], dz = sDz[r];
        float v0 = f.x + dx*sWx[c]   + dy*sWx[C1_+c]   + dz*sWx[2*C1_+c];
        float v1 = f.y + dx*sWx[c+1] + dy*sWx[C1_+c+1] + dz*sWx[2*C1_+c+1];
        v0 = fmaxf(fmaf(v0, sA1[c],   sB1[c]),   0.f);
        v1 = fmaxf(fmaf(v1, sA1[c+1], sB1[c+1]), 0.f);
        __nv_bfloat16 h0 = __float2bfloat16(v0);
        __nv_bfloat16 h1 = __float2bfloat16(v1);
        __nv_bfloat16 l0 = __float2bfloat16(v0 - __bfloat162float(h0));
        __nv_bfloat16 l1 = __float2bfloat16(v1 - __bfloat162float(h1));
        uint32_t hp = (uint32_t)*(const uint16_t*)&h0 | ((uint32_t)*(const uint16_t*)&h1 << 16);
        uint32_t lp = (uint32_t)*(const uint16_t*)&l0 | ((uint32_t)*(const uint16_t*)&l1 << 16);
        uint32_t off = SW128((uint32_t)(r*128 + c*2));
        *(uint32_t*)(al + off)           = hp;
        *(uint32_t*)(al + OFF_ALO + off) = lp;
    }
    __syncthreads();

    // warp tiling: 4 row-warps x 2 col-warps; warp tile = 32 rows (one query) x 64 cols
    int w_r = wid & 3, w_c = wid >> 2;
    uint32_t Ah = abase, Al = abase + OFF_ALO;
    uint32_t Bh = abase + OFF_BHI, Bl = abase + OFF_BLO;

    int rowA = w_r*32 + (lane & 15);
    int kbA  = (lane >> 4) * 16;
    int nB   = w_c*64 + ((lane >> 4) << 3) + (lane & 7);
    int kbB  = ((lane >> 3) & 1) * 16;

    float acc[2][8][4];
#pragma unroll
    for (int mt = 0; mt < 2; mt++)
#pragma unroll
        for (int nt = 0; nt < 8; nt++)
#pragma unroll
            for (int j = 0; j < 4; j++) acc[mt][nt][j] = 0.f;

#pragma unroll
    for (int ks = 0; ks < 4; ks++) {
        uint32_t oA[2], oB[4];
#pragma unroll
        for (int mt = 0; mt < 2; mt++)
            oA[mt] = SW128((uint32_t)((rowA + mt*16)*128 + ks*32 + kbA));
#pragma unroll
        for (int np = 0; np < 4; np++)
            oB[np] = SW128((uint32_t)((nB + np*16)*128 + ks*32 + kbB));

        uint32_t ah[2][4], alr[2][4], bb[4][4];
#pragma unroll
        for (int mt = 0; mt < 2; mt++) ldsm_x4(ah[mt],  Ah + oA[mt]);
#pragma unroll
        for (int mt = 0; mt < 2; mt++) ldsm_x4(alr[mt], Al + oA[mt]);
#pragma unroll
        for (int np = 0; np < 4; np++) ldsm_x4(bb[np],  Bh + oB[np]);
        // Ahi*Bhi + Alo*Bhi while Bhi is resident
#pragma unroll
        for (int mt = 0; mt < 2; mt++)
#pragma unroll
            for (int nt = 0; nt < 8; nt++)
                mma_bf16(acc[mt][nt], ah[mt], &bb[nt >> 1][(nt & 1) * 2]);
#pragma unroll
        for (int mt = 0; mt < 2; mt++)
#pragma unroll
            for (int nt = 0; nt < 8; nt++)
                mma_bf16(acc[mt][nt], alr[mt], &bb[nt >> 1][(nt & 1) * 2]);
        // Ahi*Blo
#pragma unroll
        for (int np = 0; np < 4; np++) ldsm_x4(bb[np], Bl + oB[np]);
#pragma unroll
        for (int mt = 0; mt < 2; mt++)
#pragma unroll
            for (int nt = 0; nt < 8; nt++)
                mma_bf16(acc[mt][nt], ah[mt], &bb[nt >> 1][(nt & 1) * 2]);
    }

    // epilogue: reduce each column over the warp's 32 rows (one query)
    int bnq = bn0 + w_r;
#pragma unroll
    for (int nt = 0; nt < 8; nt++) {
        float a0 = acc[0][nt][0], a2 = acc[0][nt][2], c0v = acc[1][nt][0], c2v = acc[1][nt][2];
        float a1 = acc[0][nt][1], a3 = acc[0][nt][3], c1v = acc[1][nt][1], c3v = acc[1][nt][3];
        float mx0 = fmaxf(fmaxf(a0, a2), fmaxf(c0v, c2v));
        float mn0 = fminf(fminf(a0, a2), fminf(c0v, c2v));
        float s0  = (a0 + a2) + (c0v + c2v);
        float q0  = fmaf(a0,a0, fmaf(a2,a2, fmaf(c0v,c0v, c2v*c2v)));
        float mx1 = fmaxf(fmaxf(a1, a3), fmaxf(c1v, c3v));
        float mn1 = fminf(fminf(a1, a3), fminf(c1v, c3v));
        float s1  = (a1 + a3) + (c1v + c3v);
        float q1  = fmaf(a1,a1, fmaf(a3,a3, fmaf(c1v,c1v, c3v*c3v)));
#pragma unroll
        for (int m = 4; m < 32; m <<= 1) {
            mx0 = fmaxf(mx0, __shfl_xor_sync(0xffffffffu, mx0, m));
            mn0 = fminf(mn0, __shfl_xor_sync(0xffffffffu, mn0, m));
            s0 += __shfl_xor_sync(0xffffffffu, s0, m);
            q0 += __shfl_xor_sync(0xffffffffu, q0, m);
            mx1 = fmaxf(mx1, __shfl_xor_sync(0xffffffffu, mx1, m));
            mn1 = fminf(mn1, __shfl_xor_sync(0xffffffffu, mn1, m));
            s1 += __shfl_xor_sync(0xffffffffu, s1, m);
            q1 += __shfl_xor_sync(0xffffffffu, q1, m);
        }
        if (lane < 4) {
            int c = w_c*64 + nt*8 + 2*lane;
            *(float2*)&g_mx[(size_t)bnq*C2_ + c] = make_float2(mx0, mx1);
            *(float2*)&g_mn[(size_t)bnq*C2_ + c] = make_float2(mn0, mn1);
            atomicAdd(&ssum[c],   s0);
            atomicAdd(&ssum[c+1], s1);
            atomicAdd(&ssq [c],   q0);
            atomicAdd(&ssq [c+1], q1);
        }
    }
    __syncthreads();
    if (t < C2_) {
        atomicAdd(&g_sum2[t], (double)ssum[t]);
        atomicAdd(&g_sq2 [t], (double)ssq [t]);
    }
}

// ---------------- 4) epilogue (BN2 coefficients computed inline per block) ----------------
__global__ void k_out(const float* __restrict__ gamma2, const float* __restrict__ beta2,
                      float* __restrict__ out) {
    __shared__ float a2s[C2_], b2s[C2_];
    int t = threadIdx.x;
    if (t < C2_) {
        double mean = g_sum2[t] * RCNT_;
        double var  = g_sq2[t] * RCNT_ - mean * mean;
        float a = rsqrtf((float)var + EPS_) * gamma2[t];
        a2s[t] = a;
        b2s[t] = beta2[t] - (float)mean * a;
    }
    __syncthreads();
    int base = blockIdx.x * 2048;
#pragma unroll
    for (int j = 0; j < 8; j++) {
        int i = base + j*256 + t;
        int c = i & (C2_ - 1);
        float a = a2s[c], b = b2s[c];
        float x;
        if (a >= 0.f) x = g_mx[i]; else x = g_mn[i];
        out[i] = fmaxf(fmaf(a, x, b), 0.f);
    }
}

// ---------------- launch ----------------
extern "C" void kernel_launch(void* const* d_in, const int* in_sizes, int n_in,
                              void* d_out, int out_size) {
    const float* pos    = (const float*)d_in[0];
    const float* feat   = (const float*)d_in[1];
    const float* W1     = (const float*)d_in[2];
    const float* gamma1 = (const float*)d_in[3];
    const float* beta1  = (const float*)d_in[4];
    const float* W2     = (const float*)d_in[5];
    const float* gamma2 = (const float*)d_in[6];
    const float* beta2  = (const float*)d_in[7];
    float* out = (float*)d_out;

    cudaFuncSetAttribute(k_gemm2t, cudaFuncAttributeMaxDynamicSharedMemorySize, G2T_SMEM);

    k_init      <<<32, 256>>>(W2);
    k_f1        <<<BN_/32, 256>>>(feat, W1);
    k_ballstats <<<B_*(N_/32), 256>>>(pos, W1);
    k_gemm2t    <<<BN_/4, 256, G2T_SMEM>>>(pos, W1, gamma1, beta1);
    k_out       <<<BN_*C2_/2048, 256>>>(gamma2, beta2, out + BN_*3);
    cudaMemcpyAsync(out, pos, (size_t)BN_*3*sizeof(float),
                    cudaMemcpyDeviceToDevice);
}

// round 7
// speedup vs baseline: 2.1625x; 1.2243x over previous
#include <cuda_runtime.h>
#include <cuda_fp16.h>
#include <cstdint>

#define B_   8
#define N_   2048
#define K_   32
#define D_   64
#define C1_  64
#define C2_  128
#define BN_  (B_*N_)
#define R2_  0.0225f
#define EPS_ 1e-5f
#define RCNT_ (1.0/524288.0)   /* exact: 2^-19 */

typedef unsigned long long ull;

// ---------------- helpers ----------------
__device__ __forceinline__ uint32_t smem_u32(const void* p) {
    uint32_t a;
    asm("{ .reg .u64 t; cvta.to.shared.u64 t, %1; cvt.u32.u64 %0, t; }" : "=r"(a) : "l"(p));
    return a;
}
#define SW128(off) ((off) ^ (((off) >> 3) & 0x70))

__device__ __forceinline__ void mma_f16(float* d, const uint32_t* a, const uint32_t* b) {
    asm volatile(
        "mma.sync.aligned.m16n8k16.row.col.f32.f16.f16.f32 "
        "{%0,%1,%2,%3}, {%4,%5,%6,%7}, {%8,%9}, {%0,%1,%2,%3};"
        : "+f"(d[0]), "+f"(d[1]), "+f"(d[2]), "+f"(d[3])
        : "r"(a[0]), "r"(a[1]), "r"(a[2]), "r"(a[3]), "r"(b[0]), "r"(b[1]));
}
__device__ __forceinline__ void ldsm_x4(uint32_t* r, uint32_t addr) {
    asm volatile("ldmatrix.sync.aligned.m8n8.x4.shared.b16 {%0,%1,%2,%3}, [%4];"
        : "=r"(r[0]), "=r"(r[1]), "=r"(r[2]), "=r"(r[3]) : "r"(addr));
}

// packed fp32x2 helpers (k_f1)
__device__ __forceinline__ void fma2(ull& d, ull a, ull b) {
    asm("fma.rn.f32x2 %0, %1, %2, %0;" : "+l"(d) : "l"(a), "l"(b));
}
__device__ __forceinline__ ull pack2(float x, float y) {
    ull r; asm("mov.b64 %0, {%1, %2};" : "=l"(r) : "f"(x), "f"(y)); return r;
}
__device__ __forceinline__ void unpack2(float& x, float& y, ull v) {
    asm("mov.b64 {%0, %1}, %2;" : "=f"(x), "=f"(y) : "l"(v));
}

// ---------------- device scratch ----------------
__device__ int    g_idx[BN_*K_];
__device__ float  g_F1[BN_*C1_];
__device__ double g_sum1[C1_], g_sq1[C1_];
__device__ double g_sum2[C2_], g_sq2[C2_];
__device__ float  g_mx[BN_*C2_];
__device__ float  g_mn[BN_*C2_];
__device__ __half g_W2t[C2_*D_];   // [n][k] transposed W2, fp16

// ---------------- 0) init: zero stats + transpose W2 to fp16 ----------------
__global__ void k_init(const float* __restrict__ W2) {
    int t = threadIdx.x;
    if (blockIdx.x == 0) {
        if (t < C1_) { g_sum1[t] = 0.0; g_sq1[t] = 0.0; }
        if (t < C2_) { g_sum2[t] = 0.0; g_sq2[t] = 0.0; }
    }
    int i = blockIdx.x * 256 + t;
    if (i < D_*C2_) {
        int k = i >> 7, n = i & 127;
        g_W2t[n*D_ + k] = __float2half_rn(W2[i]);
    }
}

// ---------------- 1) F1 = feature @ W1[3:,:] ----------------
__global__ void k_f1(const float* __restrict__ feat, const float* __restrict__ W1) {
    __shared__ float sW[D_][C1_];
    __shared__ float sIn[32][D_+1];
    int row0 = blockIdx.x * 32;
    for (int i = threadIdx.x; i < D_*C1_; i += 256)
        sW[i / C1_][i % C1_] = W1[(3 + i / C1_) * C1_ + (i % C1_)];
    for (int i = threadIdx.x; i < 32*D_; i += 256)
        sIn[i / D_][i % D_] = feat[(size_t)(row0 + i / D_) * D_ + (i % D_)];
    __syncthreads();
    int k = threadIdx.x >> 3, c0 = (threadIdx.x & 7) << 3;
    ull acc[4];
#pragma unroll
    for (int j = 0; j < 4; j++) acc[j] = 0ull;
    for (int i = 0; i < D_; i++) {
        ull a = pack2(sIn[k][i], sIn[k][i]);
        const ull* wr = (const ull*)&sW[i][c0];
#pragma unroll
        for (int j = 0; j < 4; j++) fma2(acc[j], a, wr[j]);
    }
    float* o = &g_F1[(size_t)(row0 + k) * C1_ + c0];
#pragma unroll
    for (int j = 0; j < 4; j++) { float x, y; unpack2(x, y, acc[j]); o[2*j] = x; o[2*j+1] = y; }
}

// ---------------- 2) fused ball query + h1 stats ----------------
__global__ void k_ballstats(const float* __restrict__ pos, const float* __restrict__ W1) {
    __shared__ float sx[N_], sy[N_], sz[N_], sn[N_];
    __shared__ int   sbuf[8][K_];
    __shared__ float ssum[C1_], ssq[C1_];
    int t = threadIdx.x;
    int b    = blockIdx.x >> 6;
    int qblk = blockIdx.x & 63;
    const float* p = pos + (size_t)b * N_ * 3;
    for (int i = t; i < N_; i += 256) {
        float x = p[3*i], y = p[3*i+1], z = p[3*i+2];
        sx[i] = x; sy[i] = y; sz[i] = z; sn[i] = x*x + y*y + z*z;
    }
    if (t < C1_) { ssum[t] = 0.f; ssq[t] = 0.f; }
    __syncthreads();

    int w = t >> 5, lane = t & 31;
    int* buf = sbuf[w];
    float wx0 = W1[2*lane],       wx1 = W1[2*lane+1];
    float wy0 = W1[C1_+2*lane],   wy1 = W1[C1_+2*lane+1];
    float wz0 = W1[2*C1_+2*lane], wz1 = W1[2*C1_+2*lane+1];
    const float* F1b = g_F1 + (size_t)b * N_ * C1_;

    float s0 = 0.f, s1 = 0.f, q0 = 0.f, q1 = 0.f;
    for (int qq = 0; qq < 4; qq++) {
        int q = qblk * 32 + w * 4 + qq;
        float qx = sx[q], qy = sy[q], qz = sz[q], qn = sn[q];
        int cnt = 0;
        for (int base = 0; base < N_ && cnt < K_; base += 32) {
            int m = base + lane;
            float dot = qx*sx[m] + qy*sy[m] + qz*sz[m];
            float sq  = qn + sn[m] - 2.0f*dot;
            bool in   = (sq <= R2_);
            unsigned mask = __ballot_sync(0xffffffffu, in);
            if (in) {
                int pslot = cnt + __popc(mask & ((1u << lane) - 1u));
                if (pslot < K_) buf[pslot] = m;
            }
            cnt += __popc(mask);
        }
        __syncwarp();
        int v = (lane < cnt) ? buf[lane] : buf[0];
        g_idx[(b*N_ + q)*K_ + lane] = v;
        __syncwarp();

#pragma unroll 8
        for (int k = 0; k < K_; k++) {
            int m = __shfl_sync(0xffffffffu, v, k);
            float dx = sx[m] - qx, dy = sy[m] - qy, dz = sz[m] - qz;
            float2 f = *(const float2*)(F1b + (size_t)m * C1_ + 2*lane);
            float v0 = f.x + dx*wx0 + dy*wy0 + dz*wz0;
            float v1 = f.y + dx*wx1 + dy*wy1 + dz*wz1;
            s0 += v0; q0 = fmaf(v0, v0, q0);
            s1 += v1; q1 = fmaf(v1, v1, q1);
        }
    }
    atomicAdd(&ssum[2*lane],   s0);
    atomicAdd(&ssum[2*lane+1], s1);
    atomicAdd(&ssq [2*lane],   q0);
    atomicAdd(&ssq [2*lane+1], q1);
    __syncthreads();
    if (t < C1_) {
        atomicAdd(&g_sum1[t], (double)ssum[t]);
        atomicAdd(&g_sq1 [t], (double)ssq [t]);
    }
}

// ---------------- 3) HMMA gemm2: fp16 2-product split, tree epilogue ----------------
// smem (1024-aligned): Ahi [0,16K), Alo [16K,32K), B [32K,48K), extras [48K,...)
#define OFF_ALO  16384
#define OFF_B    32768
#define OFF_EX   49152
#define G2T_SMEM (OFF_EX + 1088*4 + 1024)

extern __shared__ char dynraw[];
__global__ __launch_bounds__(256, 2)
void k_gemm2t(const float* __restrict__ pos, const float* __restrict__ W1,
              const float* __restrict__ gamma1, const float* __restrict__ beta1) {
    uint32_t rawb  = smem_u32(dynraw);
    uint32_t abase = (rawb + 1023) & ~1023u;
    char*    al    = dynraw + (abase - rawb);
    float*   ex    = (float*)(al + OFF_EX);

    float* sWx  = ex;          // 192
    float* sA1  = ex + 192;    // 64
    float* sB1  = ex + 256;    // 64
    float* sDx  = ex + 320;    // 128
    float* sDy  = ex + 448;
    float* sDz  = ex + 576;
    int*   sM   = (int*)(ex + 704);   // 128
    float* ssum = ex + 832;    // 128
    float* ssq  = ex + 960;    // 128

    int t   = threadIdx.x;
    int wid = t >> 5, lane = t & 31;
    int bn0 = blockIdx.x * 4;

    if (t < 3*C1_) sWx[t] = W1[t];
    if (t < C1_) {
        double mean = g_sum1[t] * RCNT_;
        double var  = g_sq1[t] * RCNT_ - mean * mean;
        float a = rsqrtf((float)var + EPS_) * gamma1[t];
        sA1[t] = a;
        sB1[t] = beta1[t] - (float)mean * a;
    }
    if (t < C2_)   { ssum[t] = 0.f; ssq[t] = 0.f; }
    if (t < 128) {
        int r  = t;
        int bn = bn0 + (r >> 5);
        int k  = r & 31;
        int b  = bn >> 11;
        int m  = g_idx[bn*K_ + k];
        sM[r]  = b*N_ + m;
        float cx = pos[bn*3+0], cy = pos[bn*3+1], cz = pos[bn*3+2];
        const float* pm = pos + (size_t)(b*N_ + m) * 3;
        sDx[r] = pm[0]-cx; sDy[r] = pm[1]-cy; sDz[r] = pm[2]-cz;
    }

    // B tile: fp16 single, SW128 (8B chunks preserved by swizzle)
    for (int i = t; i < 128*16; i += 256) {
        int n = i >> 4, k8 = i & 15;
        uint32_t off = SW128((uint32_t)(n*128 + k8*8));
        *(ull*)(al + OFF_B + off) = ((const ull*)g_W2t)[i];
    }
    __syncthreads();

    // A tiles: h1n = relu(a1*h1+b1), fp16 2-way split
    for (int i = t; i < 128*32; i += 256) {
        int r = i >> 5, c = (i & 31) * 2;
        float2 f = *(const float2*)(g_F1 + (size_t)sM[r]*C1_ + c);
        float dx = sDx[r], dy = sDy[r], dz = sDz[r];
        float v0 = f.x + dx*sWx[c]   + dy*sWx[C1_+c]   + dz*sWx[2*C1_+c];
        float v1 = f.y + dx*sWx[c+1] + dy*sWx[C1_+c+1] + dz*sWx[2*C1_+c+1];
        v0 = fmaxf(fmaf(v0, sA1[c],   sB1[c]),   0.f);
        v1 = fmaxf(fmaf(v1, sA1[c+1], sB1[c+1]), 0.f);
        __half h0 = __float2half_rn(v0);
        __half h1 = __float2half_rn(v1);
        __half l0 = __float2half_rn(v0 - __half2float(h0));
        __half l1 = __float2half_rn(v1 - __half2float(h1));
        uint32_t hp = (uint32_t)*(const uint16_t*)&h0 | ((uint32_t)*(const uint16_t*)&h1 << 16);
        uint32_t lp = (uint32_t)*(const uint16_t*)&l0 | ((uint32_t)*(const uint16_t*)&l1 << 16);
        uint32_t off = SW128((uint32_t)(r*128 + c*2));
        *(uint32_t*)(al + off)           = hp;
        *(uint32_t*)(al + OFF_ALO + off) = lp;
    }
    __syncthreads();

    // warp tiling: 4 row-warps x 2 col-warps; warp tile = 32 rows (one query) x 64 cols
    int w_r = wid & 3, w_c = wid >> 2;
    uint32_t Ah = abase, Al = abase + OFF_ALO, Bb = abase + OFF_B;

    int rowA = w_r*32 + (lane & 15);
    int kbA  = (lane >> 4) * 16;
    int nB   = w_c*64 + ((lane >> 4) << 3) + (lane & 7);
    int kbB  = ((lane >> 3) & 1) * 16;

    float acc[2][8][4];
#pragma unroll
    for (int mt = 0; mt < 2; mt++)
#pragma unroll
        for (int nt = 0; nt < 8; nt++)
#pragma unroll
            for (int j = 0; j < 4; j++) acc[mt][nt][j] = 0.f;

#pragma unroll
    for (int ks = 0; ks < 4; ks++) {
        uint32_t oA[2], oB[4];
#pragma unroll
        for (int mt = 0; mt < 2; mt++)
            oA[mt] = SW128((uint32_t)((rowA + mt*16)*128 + ks*32 + kbA));
#pragma unroll
        for (int np = 0; np < 4; np++)
            oB[np] = SW128((uint32_t)((nB + np*16)*128 + ks*32 + kbB));

        uint32_t ah[2][4], alr[2][4], bb[4][4];
#pragma unroll
        for (int mt = 0; mt < 2; mt++) ldsm_x4(ah[mt],  Ah + oA[mt]);
#pragma unroll
        for (int mt = 0; mt < 2; mt++) ldsm_x4(alr[mt], Al + oA[mt]);
#pragma unroll
        for (int np = 0; np < 4; np++) ldsm_x4(bb[np],  Bb + oB[np]);
        // Ahi*B then Alo*B (B resident)
#pragma unroll
        for (int mt = 0; mt < 2; mt++)
#pragma unroll
            for (int nt = 0; nt < 8; nt++)
                mma_f16(acc[mt][nt], ah[mt], &bb[nt >> 1][(nt & 1) * 2]);
#pragma unroll
        for (int mt = 0; mt < 2; mt++)
#pragma unroll
            for (int nt = 0; nt < 8; nt++)
                mma_f16(acc[mt][nt], alr[mt], &bb[nt >> 1][(nt & 1) * 2]);
    }

    // ---- epilogue: in-thread reduce, then split-ownership tree over 8 lane-groups ----
    float MX[16], MN[16], S[16], Q[16];
#pragma unroll
    for (int nt = 0; nt < 8; nt++) {
        float a0 = acc[0][nt][0], a2 = acc[0][nt][2], b0 = acc[1][nt][0], b2 = acc[1][nt][2];
        MX[2*nt]   = fmaxf(fmaxf(a0, a2), fmaxf(b0, b2));
        MN[2*nt]   = fminf(fminf(a0, a2), fminf(b0, b2));
        S [2*nt]   = (a0 + a2) + (b0 + b2);
        Q [2*nt]   = fmaf(a0,a0, fmaf(a2,a2, fmaf(b0,b0, b2*b2)));
        float a1 = acc[0][nt][1], a3 = acc[0][nt][3], b1 = acc[1][nt][1], b3 = acc[1][nt][3];
        MX[2*nt+1] = fmaxf(fmaxf(a1, a3), fmaxf(b1, b3));
        MN[2*nt+1] = fminf(fminf(a1, a3), fminf(b1, b3));
        S [2*nt+1] = (a1 + a3) + (b1 + b3);
        Q [2*nt+1] = fmaf(a1,a1, fmaf(a3,a3, fmaf(b1,b1, b3*b3)));
    }
#pragma unroll
    for (int st = 0; st < 3; st++) {
        int d   = 4 << st;      // 4, 8, 16
        int len = 8 >> st;      // 8, 4, 2
        bool up = (lane & d) != 0;
#pragma unroll
        for (int tt = 0; tt < 8; tt++) {
            if (tt >= len) break;
            float sx_, rx, sn_, rn, ss_, rs, sq_, rq;
            sx_ = up ? MX[tt] : MX[tt+len]; rx = __shfl_xor_sync(0xffffffffu, sx_, d);
            MX[tt] = up ? fmaxf(MX[tt+len], rx) : fmaxf(MX[tt], rx);
            sn_ = up ? MN[tt] : MN[tt+len]; rn = __shfl_xor_sync(0xffffffffu, sn_, d);
            MN[tt] = up ? fminf(MN[tt+len], rn) : fminf(MN[tt], rn);
            ss_ = up ? S[tt] : S[tt+len];   rs = __shfl_xor_sync(0xffffffffu, ss_, d);
            S[tt]  = (up ? S[tt+len] : S[tt]) + rs;
            sq_ = up ? Q[tt] : Q[tt+len];   rq = __shfl_xor_sync(0xffffffffu, sq_, d);
            Q[tt]  = (up ? Q[tt+len] : Q[tt]) + rq;
        }
    }
    // lane owns original vars v0, v0+1
    int v0 = ((lane >> 2) & 1) * 8 + ((lane >> 3) & 1) * 4 + ((lane >> 4) & 1) * 2;
    int c0 = w_c*64 + (v0 >> 1) * 8 + 2*(lane & 3);
    int bnq = bn0 + w_r;
    *(float2*)&g_mx[(size_t)bnq*C2_ + c0] = make_float2(MX[0], MX[1]);
    *(float2*)&g_mn[(size_t)bnq*C2_ + c0] = make_float2(MN[0], MN[1]);
    atomicAdd(&ssum[c0],   S[0]);
    atomicAdd(&ssum[c0+1], S[1]);
    atomicAdd(&ssq [c0],   Q[0]);
    atomicAdd(&ssq [c0+1], Q[1]);

    __syncthreads();
    if (t < C2_) {
        atomicAdd(&g_sum2[t], (double)ssum[t]);
        atomicAdd(&g_sq2 [t], (double)ssq [t]);
    }
}

// ---------------- 4) epilogue (BN2 inline per block) ----------------
__global__ void k_out(const float* __restrict__ gamma2, const float* __restrict__ beta2,
                      float* __restrict__ out) {
    __shared__ float a2s[C2_], b2s[C2_];
    int t = threadIdx.x;
    if (t < C2_) {
        double mean = g_sum2[t] * RCNT_;
        double var  = g_sq2[t] * RCNT_ - mean * mean;
        float a = rsqrtf((float)var + EPS_) * gamma2[t];
        a2s[t] = a;
        b2s[t] = beta2[t] - (float)mean * a;
    }
    __syncthreads();
    int base = blockIdx.x * 2048;
#pragma unroll
    for (int j = 0; j < 8; j++) {
        int i = base + j*256 + t;
        int c = i & (C2_ - 1);
        float a = a2s[c], b = b2s[c];
        float x = (a >= 0.f) ? g_mx[i] : g_mn[i];
        out[i] = fmaxf(fmaf(a, x, b), 0.f);
    }
}

// ---------------- launch ----------------
extern "C" void kernel_launch(void* const* d_in, const int* in_sizes, int n_in,
                              void* d_out, int out_size) {
    const float* pos    = (const float*)d_in[0];
    const float* feat   = (const float*)d_in[1];
    const float* W1     = (const float*)d_in[2];
    const float* gamma1 = (const float*)d_in[3];
    const float* beta1  = (const float*)d_in[4];
    const float* W2     = (const float*)d_in[5];
    const float* gamma2 = (const float*)d_in[6];
    const float* beta2  = (const float*)d_in[7];
    float* out = (float*)d_out;

    cudaFuncSetAttribute(k_gemm2t, cudaFuncAttributeMaxDynamicSharedMemorySize, G2T_SMEM);

    k_init      <<<32, 256>>>(W2);
    k_f1        <<<BN_/32, 256>>>(feat, W1);
    k_ballstats <<<B_*(N_/32), 256>>>(pos, W1);
    k_gemm2t    <<<BN_/4, 256, G2T_SMEM>>>(pos, W1, gamma1, beta1);
    k_out       <<<BN_*C2_/2048, 256>>>(gamma2, beta2, out + BN_*3);
    cudaMemcpyAsync(out, pos, (size_t)BN_*3*sizeof(float),
                    cudaMemcpyDeviceToDevice);
}

// round 8
// speedup vs baseline: 2.4080x; 1.1135x over previous
#include <cuda_runtime.h>
#include <cuda_fp16.h>
#include <cstdint>

#define B_   8
#define N_   2048
#define K_   32
#define D_   64
#define C1_  64
#define C2_  128
#define BN_  (B_*N_)
#define R2_  0.0225f
#define EPS_ 1e-5f
#define RCNT_ (1.0/524288.0)   /* exact: 2^-19 */

typedef unsigned long long ull;

// ---------------- helpers ----------------
__device__ __forceinline__ uint32_t smem_u32(const void* p) {
    uint32_t a;
    asm("{ .reg .u64 t; cvta.to.shared.u64 t, %1; cvt.u32.u64 %0, t; }" : "=r"(a) : "l"(p));
    return a;
}
#define SW128(off) ((off) ^ (((off) >> 3) & 0x70))

__device__ __forceinline__ void mma_f16(float* d, const uint32_t* a, const uint32_t* b) {
    asm volatile(
        "mma.sync.aligned.m16n8k16.row.col.f32.f16.f16.f32 "
        "{%0,%1,%2,%3}, {%4,%5,%6,%7}, {%8,%9}, {%0,%1,%2,%3};"
        : "+f"(d[0]), "+f"(d[1]), "+f"(d[2]), "+f"(d[3])
        : "r"(a[0]), "r"(a[1]), "r"(a[2]), "r"(a[3]), "r"(b[0]), "r"(b[1]));
}
__device__ __forceinline__ void ldsm_x4(uint32_t* r, uint32_t addr) {
    asm volatile("ldmatrix.sync.aligned.m8n8.x4.shared.b16 {%0,%1,%2,%3}, [%4];"
        : "=r"(r[0]), "=r"(r[1]), "=r"(r[2]), "=r"(r[3]) : "r"(addr));
}

// packed fp32x2 helpers (k_f1)
__device__ __forceinline__ void fma2(ull& d, ull a, ull b) {
    asm("fma.rn.f32x2 %0, %1, %2, %0;" : "+l"(d) : "l"(a), "l"(b));
}
__device__ __forceinline__ ull pack2(float x, float y) {
    ull r; asm("mov.b64 %0, {%1, %2};" : "=l"(r) : "f"(x), "f"(y)); return r;
}
__device__ __forceinline__ void unpack2(float& x, float& y, ull v) {
    asm("mov.b64 {%0, %1}, %2;" : "=f"(x), "=f"(y) : "l"(v));
}

// ---------------- device scratch ----------------
__device__ int    g_idx[BN_*K_];
__device__ float  g_F1[BN_*C1_];
__device__ double g_sum1[C1_], g_sq1[C1_];
__device__ double g_sum2[C2_], g_sq2[C2_];
__device__ float  g_mx[BN_*C2_];
__device__ float  g_mn[BN_*C2_];
__device__ __half g_W2t[C2_*D_];   // [n][k] transposed W2, fp16

// ---------------- 0) init ----------------
__global__ void k_init(const float* __restrict__ W2) {
    int t = threadIdx.x;
    if (blockIdx.x == 0) {
        if (t < C1_) { g_sum1[t] = 0.0; g_sq1[t] = 0.0; }
        if (t < C2_) { g_sum2[t] = 0.0; g_sq2[t] = 0.0; }
    }
    int i = blockIdx.x * 256 + t;
    if (i < D_*C2_) {
        int k = i >> 7, n = i & 127;
        g_W2t[n*D_ + k] = __float2half_rn(W2[i]);
    }
}

// ---------------- 1) F1 = feature @ W1[3:,:] ----------------
__global__ void k_f1(const float* __restrict__ feat, const float* __restrict__ W1) {
    __shared__ float sW[D_][C1_];
    __shared__ float sIn[32][D_+1];
    int row0 = blockIdx.x * 32;
    for (int i = threadIdx.x; i < D_*C1_; i += 256)
        sW[i / C1_][i % C1_] = W1[(3 + i / C1_) * C1_ + (i % C1_)];
    for (int i = threadIdx.x; i < 32*D_; i += 256)
        sIn[i / D_][i % D_] = feat[(size_t)(row0 + i / D_) * D_ + (i % D_)];
    __syncthreads();
    int k = threadIdx.x >> 3, c0 = (threadIdx.x & 7) << 3;
    ull acc[4];
#pragma unroll
    for (int j = 0; j < 4; j++) acc[j] = 0ull;
    for (int i = 0; i < D_; i++) {
        ull a = pack2(sIn[k][i], sIn[k][i]);
        const ull* wr = (const ull*)&sW[i][c0];
#pragma unroll
        for (int j = 0; j < 4; j++) fma2(acc[j], a, wr[j]);
    }
    float* o = &g_F1[(size_t)(row0 + k) * C1_ + c0];
#pragma unroll
    for (int j = 0; j < 4; j++) { float x, y; unpack2(x, y, acc[j]); o[2*j] = x; o[2*j+1] = y; }
}

// ---------------- 2) fused ball query + h1 stats ----------------
__global__ void k_ballstats(const float* __restrict__ pos, const float* __restrict__ W1) {
    __shared__ float sx[N_], sy[N_], sz[N_], sn[N_];
    __shared__ int   sbuf[8][K_];
    __shared__ float ssum[C1_], ssq[C1_];
    int t = threadIdx.x;
    int b    = blockIdx.x >> 6;
    int qblk = blockIdx.x & 63;
    const float* p = pos + (size_t)b * N_ * 3;
    for (int i = t; i < N_; i += 256) {
        float x = p[3*i], y = p[3*i+1], z = p[3*i+2];
        sx[i] = x; sy[i] = y; sz[i] = z; sn[i] = x*x + y*y + z*z;
    }
    if (t < C1_) { ssum[t] = 0.f; ssq[t] = 0.f; }
    __syncthreads();

    int w = t >> 5, lane = t & 31;
    int* buf = sbuf[w];
    float wx0 = W1[2*lane],       wx1 = W1[2*lane+1];
    float wy0 = W1[C1_+2*lane],   wy1 = W1[C1_+2*lane+1];
    float wz0 = W1[2*C1_+2*lane], wz1 = W1[2*C1_+2*lane+1];
    const float* F1b = g_F1 + (size_t)b * N_ * C1_;

    float s0 = 0.f, s1 = 0.f, q0 = 0.f, q1 = 0.f;
    for (int qq = 0; qq < 4; qq++) {
        int q = qblk * 32 + w * 4 + qq;
        float qx = sx[q], qy = sy[q], qz = sz[q], qn = sn[q];
        int cnt = 0;
        for (int base = 0; base < N_ && cnt < K_; base += 32) {
            int m = base + lane;
            float dot = qx*sx[m] + qy*sy[m] + qz*sz[m];
            float sq  = qn + sn[m] - 2.0f*dot;
            bool in   = (sq <= R2_);
            unsigned mask = __ballot_sync(0xffffffffu, in);
            if (in) {
                int pslot = cnt + __popc(mask & ((1u << lane) - 1u));
                if (pslot < K_) buf[pslot] = m;
            }
            cnt += __popc(mask);
        }
        __syncwarp();
        int v = (lane < cnt) ? buf[lane] : buf[0];
        g_idx[(b*N_ + q)*K_ + lane] = v;
        __syncwarp();

#pragma unroll 8
        for (int k = 0; k < K_; k++) {
            int m = __shfl_sync(0xffffffffu, v, k);
            float dx = sx[m] - qx, dy = sy[m] - qy, dz = sz[m] - qz;
            float2 f = *(const float2*)(F1b + (size_t)m * C1_ + 2*lane);
            float v0 = f.x + dx*wx0 + dy*wy0 + dz*wz0;
            float v1 = f.y + dx*wx1 + dy*wy1 + dz*wz1;
            s0 += v0; q0 = fmaf(v0, v0, q0);
            s1 += v1; q1 = fmaf(v1, v1, q1);
        }
    }
    atomicAdd(&ssum[2*lane],   s0);
    atomicAdd(&ssum[2*lane+1], s1);
    atomicAdd(&ssq [2*lane],   q0);
    atomicAdd(&ssq [2*lane+1], q1);
    __syncthreads();
    if (t < C1_) {
        atomicAdd(&g_sum1[t], (double)ssum[t]);
        atomicAdd(&g_sq1 [t], (double)ssq [t]);
    }
}

// ---------------- 3) HMMA gemm2: single-product fp16, 256 rows/block ----------------
// smem (1024-aligned): A [0,32K)  256 rows x 128B SW128; B [32K,48K); extras [48K,...)
#define A_ROWS   256
#define OFF_B    32768
#define OFF_EX   49152
#define G2T_SMEM (OFF_EX + 2048*4 + 1024)

extern __shared__ char dynraw[];
__global__ __launch_bounds__(256, 2)
void k_gemm2t(const float* __restrict__ pos, const float* __restrict__ W1,
              const float* __restrict__ gamma1, const float* __restrict__ beta1) {
    uint32_t rawb  = smem_u32(dynraw);
    uint32_t abase = (rawb + 1023) & ~1023u;
    char*    al    = dynraw + (abase - rawb);
    float*   ex    = (float*)(al + OFF_EX);

    float* sWx  = ex;          // 192
    float* sA1  = ex + 192;    // 64
    float* sB1  = ex + 256;    // 64
    float* sDx  = ex + 320;    // 256
    float* sDy  = ex + 576;    // 256
    float* sDz  = ex + 832;    // 256
    int*   sM   = (int*)(ex + 1088);  // 256
    float* ssum = ex + 1344;   // 128
    float* ssq  = ex + 1472;   // 128

    int t   = threadIdx.x;
    int wid = t >> 5, lane = t & 31;
    int bn0 = blockIdx.x * 8;          // 8 queries per block

    if (t < 3*C1_) sWx[t] = W1[t];
    if (t < C1_) {
        double mean = g_sum1[t] * RCNT_;
        double var  = g_sq1[t] * RCNT_ - mean * mean;
        float a = rsqrtf((float)var + EPS_) * gamma1[t];
        sA1[t] = a;
        sB1[t] = beta1[t] - (float)mean * a;
    }
    if (t < C2_)   { ssum[t] = 0.f; ssq[t] = 0.f; }
    {
        int r  = t;                     // 256 rows, one per thread
        int bn = bn0 + (r >> 5);
        int k  = r & 31;
        int b  = bn >> 11;
        int m  = g_idx[bn*K_ + k];
        sM[r]  = b*N_ + m;
        float cx = pos[bn*3+0], cy = pos[bn*3+1], cz = pos[bn*3+2];
        const float* pm = pos + (size_t)(b*N_ + m) * 3;
        sDx[r] = pm[0]-cx; sDy[r] = pm[1]-cy; sDz[r] = pm[2]-cz;
    }

    // B tile: fp16, SW128 (8B chunks preserved by swizzle)
    for (int i = t; i < 128*16; i += 256) {
        int n = i >> 4, k8 = i & 15;
        uint32_t off = SW128((uint32_t)(n*128 + k8*8));
        *(ull*)(al + OFF_B + off) = ((const ull*)g_W2t)[i];
    }
    __syncthreads();

    // A tile: h1n = relu(a1*h1+b1) -> fp16, 256 rows
    for (int i = t; i < A_ROWS*32; i += 256) {
        int r = i >> 5, c = (i & 31) * 2;
        float2 f = *(const float2*)(g_F1 + (size_t)sM[r]*C1_ + c);
        float dx = sDx[r], dy = sDy[r], dz = sDz[r];
        float v0 = f.x + dx*sWx[c]   + dy*sWx[C1_+c]   + dz*sWx[2*C1_+c];
        float v1 = f.y + dx*sWx[c+1] + dy*sWx[C1_+c+1] + dz*sWx[2*C1_+c+1];
        v0 = fmaxf(fmaf(v0, sA1[c],   sB1[c]),   0.f);
        v1 = fmaxf(fmaf(v1, sA1[c+1], sB1[c+1]), 0.f);
        __half h0 = __float2half_rn(v0);
        __half h1 = __float2half_rn(v1);
        uint32_t hp = (uint32_t)*(const uint16_t*)&h0 | ((uint32_t)*(const uint16_t*)&h1 << 16);
        *(uint32_t*)(al + SW128((uint32_t)(r*128 + c*2))) = hp;
    }
    __syncthreads();

    // warp tiling: 4 row-warps x 2 col-warps; two sequential 128-row groups share B
    int w_r = wid & 3, w_c = wid >> 2;
    uint32_t Aa = abase, Bb = abase + OFF_B;

    int kbA  = (lane >> 4) * 16;
    int nB   = w_c*64 + ((lane >> 4) << 3) + (lane & 7);
    int kbB  = ((lane >> 3) & 1) * 16;
    uint32_t oB[4][4];
#pragma unroll
    for (int ks = 0; ks < 4; ks++)
#pragma unroll
        for (int np = 0; np < 4; np++)
            oB[ks][np] = SW128((uint32_t)((nB + np*16)*128 + ks*32 + kbB));

#pragma unroll
    for (int g = 0; g < 2; g++) {
        int rowA = g*128 + w_r*32 + (lane & 15);

        float acc[2][8][4];
#pragma unroll
        for (int mt = 0; mt < 2; mt++)
#pragma unroll
            for (int nt = 0; nt < 8; nt++)
#pragma unroll
                for (int j = 0; j < 4; j++) acc[mt][nt][j] = 0.f;

#pragma unroll
        for (int ks = 0; ks < 4; ks++) {
            uint32_t ah[2][4], bb[4][4];
#pragma unroll
            for (int mt = 0; mt < 2; mt++)
                ldsm_x4(ah[mt], Aa + SW128((uint32_t)((rowA + mt*16)*128 + ks*32 + kbA)));
#pragma unroll
            for (int np = 0; np < 4; np++) ldsm_x4(bb[np], Bb + oB[ks][np]);
#pragma unroll
            for (int mt = 0; mt < 2; mt++)
#pragma unroll
                for (int nt = 0; nt < 8; nt++)
                    mma_f16(acc[mt][nt], ah[mt], &bb[nt >> 1][(nt & 1) * 2]);
        }

        // ---- epilogue: in-thread reduce, then split-ownership tree ----
        float MX[16], MN[16], S[16], Q[16];
#pragma unroll
        for (int nt = 0; nt < 8; nt++) {
            float a0 = acc[0][nt][0], a2 = acc[0][nt][2], b0 = acc[1][nt][0], b2 = acc[1][nt][2];
            MX[2*nt]   = fmaxf(fmaxf(a0, a2), fmaxf(b0, b2));
            MN[2*nt]   = fminf(fminf(a0, a2), fminf(b0, b2));
            S [2*nt]   = (a0 + a2) + (b0 + b2);
            Q [2*nt]   = fmaf(a0,a0, fmaf(a2,a2, fmaf(b0,b0, b2*b2)));
            float a1 = acc[0][nt][1], a3 = acc[0][nt][3], b1 = acc[1][nt][1], b3 = acc[1][nt][3];
            MX[2*nt+1] = fmaxf(fmaxf(a1, a3), fmaxf(b1, b3));
            MN[2*nt+1] = fminf(fminf(a1, a3), fminf(b1, b3));
            S [2*nt+1] = (a1 + a3) + (b1 + b3);
            Q [2*nt+1] = fmaf(a1,a1, fmaf(a3,a3, fmaf(b1,b1, b3*b3)));
        }
#pragma unroll
        for (int st = 0; st < 3; st++) {
            int d   = 4 << st;
            int len = 8 >> st;
            bool up = (lane & d) != 0;
#pragma unroll
            for (int tt = 0; tt < 8; tt++) {
                if (tt >= len) break;
                float sx_, rx, sn_, rn, ss_, rs, sq_, rq;
                sx_ = up ? MX[tt] : MX[tt+len]; rx = __shfl_xor_sync(0xffffffffu, sx_, d);
                MX[tt] = up ? fmaxf(MX[tt+len], rx) : fmaxf(MX[tt], rx);
                sn_ = up ? MN[tt] : MN[tt+len]; rn = __shfl_xor_sync(0xffffffffu, sn_, d);
                MN[tt] = up ? fminf(MN[tt+len], rn) : fminf(MN[tt], rn);
                ss_ = up ? S[tt] : S[tt+len];   rs = __shfl_xor_sync(0xffffffffu, ss_, d);
                S[tt]  = (up ? S[tt+len] : S[tt]) + rs;
                sq_ = up ? Q[tt] : Q[tt+len];   rq = __shfl_xor_sync(0xffffffffu, sq_, d);
                Q[tt]  = (up ? Q[tt+len] : Q[tt]) + rq;
            }
        }
        int v0 = ((lane >> 2) & 1) * 8 + ((lane >> 3) & 1) * 4 + ((lane >> 4) & 1) * 2;
        int c0 = w_c*64 + (v0 >> 1) * 8 + 2*(lane & 3);
        int bnq = bn0 + g*4 + w_r;
        *(float2*)&g_mx[(size_t)bnq*C2_ + c0] = make_float2(MX[0], MX[1]);
        *(float2*)&g_mn[(size_t)bnq*C2_ + c0] = make_float2(MN[0], MN[1]);
        atomicAdd(&ssum[c0],   S[0]);
        atomicAdd(&ssum[c0+1], S[1]);
        atomicAdd(&ssq [c0],   Q[0]);
        atomicAdd(&ssq [c0+1], Q[1]);
    }

    __syncthreads();
    if (t < C2_) {
        atomicAdd(&g_sum2[t], (double)ssum[t]);
        atomicAdd(&g_sq2 [t], (double)ssq [t]);
    }
}

// ---------------- 4) epilogue (BN2 inline per block) ----------------
__global__ void k_out(const float* __restrict__ gamma2, const float* __restrict__ beta2,
                      float* __restrict__ out) {
    __shared__ float a2s[C2_], b2s[C2_];
    int t = threadIdx.x;
    if (t < C2_) {
        double mean = g_sum2[t] * RCNT_;
        double var  = g_sq2[t] * RCNT_ - mean * mean;
        float a = rsqrtf((float)var + EPS_) * gamma2[t];
        a2s[t] = a;
        b2s[t] = beta2[t] - (float)mean * a;
    }
    __syncthreads();
    int base = blockIdx.x * 2048;
#pragma unroll
    for (int j = 0; j < 8; j++) {
        int i = base + j*256 + t;
        int c = i & (C2_ - 1);
        float a = a2s[c], b = b2s[c];
        float x = (a >= 0.f) ? g_mx[i] : g_mn[i];
        out[i] = fmaxf(fmaf(a, x, b), 0.f);
    }
}

// ---------------- launch ----------------
extern "C" void kernel_launch(void* const* d_in, const int* in_sizes, int n_in,
                              void* d_out, int out_size) {
    const float* pos    = (const float*)d_in[0];
    const float* feat   = (const float*)d_in[1];
    const float* W1     = (const float*)d_in[2];
    const float* gamma1 = (const float*)d_in[3];
    const float* beta1  = (const float*)d_in[4];
    const float* W2     = (const float*)d_in[5];
    const float* gamma2 = (const float*)d_in[6];
    const float* beta2  = (const float*)d_in[7];
    float* out = (float*)d_out;

    cudaFuncSetAttribute(k_gemm2t, cudaFuncAttributeMaxDynamicSharedMemorySize, G2T_SMEM);

    k_init      <<<32, 256>>>(W2);
    k_f1        <<<BN_/32, 256>>>(feat, W1);
    k_ballstats <<<B_*(N_/32), 256>>>(pos, W1);
    k_gemm2t    <<<BN_/8, 256, G2T_SMEM>>>(pos, W1, gamma1, beta1);
    k_out       <<<BN_*C2_/2048, 256>>>(gamma2, beta2, out + BN_*3);
    cudaMemcpyAsync(out, pos, (size_t)BN_*3*sizeof(float),
                    cudaMemcpyDeviceToDevice);
}

// round 9
// speedup vs baseline: 2.6057x; 1.0821x over previous
#include <cuda_runtime.h>
#include <cuda_fp16.h>
#include <cstdint>

#define B_   8
#define N_   2048
#define K_   32
#define D_   64
#define C1_  64
#define C2_  128
#define BN_  (B_*N_)
#define R2_  0.0225f
#define EPS_ 1e-5f
#define RCNT_ (1.0/524288.0)   /* exact: 2^-19 */

typedef unsigned long long ull;

// ---------------- helpers ----------------
__device__ __forceinline__ uint32_t smem_u32(const void* p) {
    uint32_t a;
    asm("{ .reg .u64 t; cvta.to.shared.u64 t, %1; cvt.u32.u64 %0, t; }" : "=r"(a) : "l"(p));
    return a;
}
#define SW128(off) ((off) ^ (((off) >> 3) & 0x70))

__device__ __forceinline__ void mma_f16(float* d, const uint32_t* a, const uint32_t* b) {
    asm volatile(
        "mma.sync.aligned.m16n8k16.row.col.f32.f16.f16.f32 "
        "{%0,%1,%2,%3}, {%4,%5,%6,%7}, {%8,%9}, {%0,%1,%2,%3};"
        : "+f"(d[0]), "+f"(d[1]), "+f"(d[2]), "+f"(d[3])
        : "r"(a[0]), "r"(a[1]), "r"(a[2]), "r"(a[3]), "r"(b[0]), "r"(b[1]));
}
__device__ __forceinline__ void ldsm_x4(uint32_t* r, uint32_t addr) {
    asm volatile("ldmatrix.sync.aligned.m8n8.x4.shared.b16 {%0,%1,%2,%3}, [%4];"
        : "=r"(r[0]), "=r"(r[1]), "=r"(r[2]), "=r"(r[3]) : "r"(addr));
}

// packed fp32x2 helpers (k_f1)
__device__ __forceinline__ void fma2(ull& d, ull a, ull b) {
    asm("fma.rn.f32x2 %0, %1, %2, %0;" : "+l"(d) : "l"(a), "l"(b));
}
__device__ __forceinline__ ull pack2(float x, float y) {
    ull r; asm("mov.b64 %0, {%1, %2};" : "=l"(r) : "f"(x), "f"(y)); return r;
}
__device__ __forceinline__ void unpack2(float& x, float& y, ull v) {
    asm("mov.b64 {%0, %1}, %2;" : "=f"(x), "=f"(y) : "l"(v));
}

// ---------------- device scratch ----------------
__device__ int    g_idx[BN_*K_];
__device__ float  g_F1[BN_*C1_];
__device__ double g_sum1[C1_], g_sq1[C1_];
__device__ double g_sum2[C2_], g_sq2[C2_];
__device__ float  g_mx[BN_*C2_];
__device__ float  g_mn[BN_*C2_];
__device__ __half g_W2t[C2_*D_];   // [n][k] transposed W2, fp16

// ---------------- 0) init ----------------
__global__ void k_init(const float* __restrict__ W2) {
    int t = threadIdx.x;
    if (blockIdx.x == 0) {
        if (t < C1_) { g_sum1[t] = 0.0; g_sq1[t] = 0.0; }
        if (t < C2_) { g_sum2[t] = 0.0; g_sq2[t] = 0.0; }
    }
    int i = blockIdx.x * 256 + t;
    if (i < D_*C2_) {
        int k = i >> 7, n = i & 127;
        g_W2t[n*D_ + k] = __float2half_rn(W2[i]);
    }
}

// ---------------- 1) F1 = feature @ W1[3:,:] ----------------
__global__ void k_f1(const float* __restrict__ feat, const float* __restrict__ W1) {
    __shared__ float sW[D_][C1_];
    __shared__ float sIn[32][D_+1];
    int row0 = blockIdx.x * 32;
    for (int i = threadIdx.x; i < D_*C1_; i += 256)
        sW[i / C1_][i % C1_] = W1[(3 + i / C1_) * C1_ + (i % C1_)];
    for (int i = threadIdx.x; i < 32*D_; i += 256)
        sIn[i / D_][i % D_] = feat[(size_t)(row0 + i / D_) * D_ + (i % D_)];
    __syncthreads();
    int k = threadIdx.x >> 3, c0 = (threadIdx.x & 7) << 3;
    ull acc[4];
#pragma unroll
    for (int j = 0; j < 4; j++) acc[j] = 0ull;
    for (int i = 0; i < D_; i++) {
        ull a = pack2(sIn[k][i], sIn[k][i]);
        const ull* wr = (const ull*)&sW[i][c0];
#pragma unroll
        for (int j = 0; j < 4; j++) fma2(acc[j], a, wr[j]);
    }
    float* o = &g_F1[(size_t)(row0 + k) * C1_ + c0];
#pragma unroll
    for (int j = 0; j < 4; j++) { float x, y; unpack2(x, y, acc[j]); o[2*j] = x; o[2*j+1] = y; }
}

// ---------------- 2) fused ball query + h1 stats (candidate-hoisted) ----------------
__global__ void k_ballstats(const float* __restrict__ pos, const float* __restrict__ W1) {
    __shared__ float sx[N_], sy[N_], sz[N_], sn[N_];
    __shared__ int   sbuf[8][4][K_];
    __shared__ float ssum[C1_], ssq[C1_];
    int t = threadIdx.x;
    int b    = blockIdx.x >> 6;
    int qblk = blockIdx.x & 63;
    const float* p = pos + (size_t)b * N_ * 3;
    for (int i = t; i < N_; i += 256) {
        float x = p[3*i], y = p[3*i+1], z = p[3*i+2];
        sx[i] = x; sy[i] = y; sz[i] = z; sn[i] = x*x + y*y + z*z;
    }
    if (t < C1_) { ssum[t] = 0.f; ssq[t] = 0.f; }
    __syncthreads();

    int w = t >> 5, lane = t & 31;
    int q0 = qblk * 32 + w * 4;
    float qx0 = sx[q0+0], qy0 = sy[q0+0], qz0 = sz[q0+0], qn0 = sn[q0+0];
    float qx1 = sx[q0+1], qy1 = sy[q0+1], qz1 = sz[q0+1], qn1 = sn[q0+1];
    float qx2 = sx[q0+2], qy2 = sy[q0+2], qz2 = sz[q0+2], qn2 = sn[q0+2];
    float qx3 = sx[q0+3], qy3 = sy[q0+3], qz3 = sz[q0+3], qn3 = sn[q0+3];
    int cnt0 = 0, cnt1 = 0, cnt2 = 0, cnt3 = 0;

    for (int base = 0; base < N_; base += 32) {
        if (cnt0 >= K_ && cnt1 >= K_ && cnt2 >= K_ && cnt3 >= K_) break;
        int m = base + lane;
        float cx = sx[m], cy = sy[m], cz = sz[m], cn = sn[m];
#define BALLQ(ii) \
        if (cnt##ii < K_) { \
            float dot = qx##ii*cx + qy##ii*cy + qz##ii*cz; \
            float sq  = qn##ii + cn - 2.0f*dot; \
            bool in   = (sq <= R2_); \
            unsigned msk = __ballot_sync(0xffffffffu, in); \
            if (in) { \
                int ps = cnt##ii + __popc(msk & ((1u << lane) - 1u)); \
                if (ps < K_) sbuf[w][ii][ps] = m; \
            } \
            cnt##ii += __popc(msk); \
        }
        BALLQ(0) BALLQ(1) BALLQ(2) BALLQ(3)
#undef BALLQ
    }
    __syncwarp();

    float wx0 = W1[2*lane],       wx1 = W1[2*lane+1];
    float wy0 = W1[C1_+2*lane],   wy1 = W1[C1_+2*lane+1];
    float wz0 = W1[2*C1_+2*lane], wz1 = W1[2*C1_+2*lane+1];
    const float* F1b = g_F1 + (size_t)b * N_ * C1_;

    float s0 = 0.f, s1 = 0.f, acq0 = 0.f, acq1 = 0.f;
    int cnts[4] = {cnt0, cnt1, cnt2, cnt3};
#pragma unroll
    for (int qq = 0; qq < 4; qq++) {
        int q = q0 + qq;
        int v = (lane < cnts[qq]) ? sbuf[w][qq][lane] : sbuf[w][qq][0];
        g_idx[(b*N_ + q)*K_ + lane] = v;
        float qx = sx[q], qy = sy[q], qz = sz[q];
#pragma unroll 8
        for (int k = 0; k < K_; k++) {
            int m = __shfl_sync(0xffffffffu, v, k);
            float dx = sx[m] - qx, dy = sy[m] - qy, dz = sz[m] - qz;
            float2 f = *(const float2*)(F1b + (size_t)m * C1_ + 2*lane);
            float v0 = f.x + dx*wx0 + dy*wy0 + dz*wz0;
            float v1 = f.y + dx*wx1 + dy*wy1 + dz*wz1;
            s0 += v0; acq0 = fmaf(v0, v0, acq0);
            s1 += v1; acq1 = fmaf(v1, v1, acq1);
        }
    }
    atomicAdd(&ssum[2*lane],   s0);
    atomicAdd(&ssum[2*lane+1], s1);
    atomicAdd(&ssq [2*lane],   acq0);
    atomicAdd(&ssq [2*lane+1], acq1);
    __syncthreads();
    if (t < C1_) {
        atomicAdd(&g_sum1[t], (double)ssum[t]);
        atomicAdd(&g_sq1 [t], (double)ssq [t]);
    }
}

// ---------------- 3) HMMA gemm2: single-product fp16, 256 rows/block ----------------
#define A_ROWS   256
#define OFF_B    32768
#define OFF_EX   49152
#define G2T_SMEM (OFF_EX + 2048*4 + 1024)

extern __shared__ char dynraw[];
__global__ __launch_bounds__(256, 2)
void k_gemm2t(const float* __restrict__ pos, const float* __restrict__ W1,
              const float* __restrict__ gamma1, const float* __restrict__ beta1) {
    uint32_t rawb  = smem_u32(dynraw);
    uint32_t abase = (rawb + 1023) & ~1023u;
    char*    al    = dynraw + (abase - rawb);
    float*   ex    = (float*)(al + OFF_EX);

    float* sWx  = ex;          // 192
    float* sA1  = ex + 192;    // 64
    float* sB1  = ex + 256;    // 64
    float* sDx  = ex + 320;    // 256
    float* sDy  = ex + 576;    // 256
    float* sDz  = ex + 832;    // 256
    int*   sM   = (int*)(ex + 1088);  // 256
    float* ssum = ex + 1344;   // 128
    float* ssq  = ex + 1472;   // 128

    int t   = threadIdx.x;
    int wid = t >> 5, lane = t & 31;
    int bn0 = blockIdx.x * 8;

    if (t < 3*C1_) sWx[t] = W1[t];
    if (t < C1_) {
        double mean = g_sum1[t] * RCNT_;
        double var  = g_sq1[t] * RCNT_ - mean * mean;
        float a = rsqrtf((float)var + EPS_) * gamma1[t];
        sA1[t] = a;
        sB1[t] = beta1[t] - (float)mean * a;
    }
    if (t < C2_)   { ssum[t] = 0.f; ssq[t] = 0.f; }
    {
        int r  = t;
        int bn = bn0 + (r >> 5);
        int k  = r & 31;
        int b  = bn >> 11;
        int m  = g_idx[bn*K_ + k];
        sM[r]  = b*N_ + m;
        float cx = pos[bn*3+0], cy = pos[bn*3+1], cz = pos[bn*3+2];
        const float* pm = pos + (size_t)(b*N_ + m) * 3;
        sDx[r] = pm[0]-cx; sDy[r] = pm[1]-cy; sDz[r] = pm[2]-cz;
    }

    // B tile: fp16, SW128
    for (int i = t; i < 128*16; i += 256) {
        int n = i >> 4, k8 = i & 15;
        uint32_t off = SW128((uint32_t)(n*128 + k8*8));
        *(ull*)(al + OFF_B + off) = ((const ull*)g_W2t)[i];
    }
    __syncthreads();

    // A tile build: fixed column-pair per thread (c-invariant values hoisted to regs),
    // loop over rows; per-iter traffic = 3 broadcast LDS + 1 coalesced LDG + 1 coalesced STS.
    {
        int c = (lane) * 2;            // 0..62, fixed per thread
        float w1x0 = sWx[c],        w1x1 = sWx[c+1];
        float w1y0 = sWx[C1_+c],    w1y1 = sWx[C1_+c+1];
        float w1z0 = sWx[2*C1_+c],  w1z1 = sWx[2*C1_+c+1];
        float a10  = sA1[c],        a11  = sA1[c+1];
        float b10  = sB1[c],        b11  = sB1[c+1];
        uint32_t stsbase = abase + 4*lane;   // byte offset of this thread's pair in a row
#pragma unroll 4
        for (int j = 0; j < 32; j++) {
            int r = wid + j*8;
            float dx = sDx[r], dy = sDy[r], dz = sDz[r];
            float2 f = *(const float2*)(g_F1 + (size_t)sM[r]*C1_ + c);
            float v0 = f.x + dx*w1x0 + dy*w1y0 + dz*w1z0;
            float v1 = f.y + dx*w1x1 + dy*w1y1 + dz*w1z1;
            v0 = fmaxf(fmaf(v0, a10, b10), 0.f);
            v1 = fmaxf(fmaf(v1, a11, b11), 0.f);
            __half h0 = __float2half_rn(v0);
            __half h1 = __float2half_rn(v1);
            uint32_t hp = (uint32_t)*(const uint16_t*)&h0 | ((uint32_t)*(const uint16_t*)&h1 << 16);
            uint32_t off = SW128((uint32_t)(r*128 + 4*lane));
            *(uint32_t*)(al + (off - 4*lane) + 4*lane) = hp;   // keep simple: direct
            (void)stsbase;
            *(uint32_t*)(al + off) = hp;
        }
    }
    __syncthreads();

    // warp tiling: 4 row-warps x 2 col-warps; two sequential 128-row groups share B
    int w_r = wid & 3, w_c = wid >> 2;
    uint32_t Aa = abase, Bb = abase + OFF_B;

    int kbA  = (lane >> 4) * 16;
    int nB   = w_c*64 + ((lane >> 4) << 3) + (lane & 7);
    int kbB  = ((lane >> 3) & 1) * 16;
    uint32_t oB[4][4];
#pragma unroll
    for (int ks = 0; ks < 4; ks++)
#pragma unroll
        for (int np = 0; np < 4; np++)
            oB[ks][np] = SW128((uint32_t)((nB + np*16)*128 + ks*32 + kbB));
    uint32_t oA[2][4][2];   // [g][ks][mt]
#pragma unroll
    for (int g = 0; g < 2; g++)
#pragma unroll
        for (int ks = 0; ks < 4; ks++)
#pragma unroll
            for (int mt = 0; mt < 2; mt++)
                oA[g][ks][mt] = SW128((uint32_t)((g*128 + w_r*32 + (lane & 15) + mt*16)*128 + ks*32 + kbA));

#pragma unroll
    for (int g = 0; g < 2; g++) {
        float acc[2][8][4];
#pragma unroll
        for (int mt = 0; mt < 2; mt++)
#pragma unroll
            for (int nt = 0; nt < 8; nt++)
#pragma unroll
                for (int j = 0; j < 4; j++) acc[mt][nt][j] = 0.f;

#pragma unroll
        for (int ks = 0; ks < 4; ks++) {
            uint32_t ah[2][4], bb[4][4];
#pragma unroll
            for (int mt = 0; mt < 2; mt++) ldsm_x4(ah[mt], Aa + oA[g][ks][mt]);
#pragma unroll
            for (int np = 0; np < 4; np++) ldsm_x4(bb[np], Bb + oB[ks][np]);
#pragma unroll
            for (int mt = 0; mt < 2; mt++)
#pragma unroll
                for (int nt = 0; nt < 8; nt++)
                    mma_f16(acc[mt][nt], ah[mt], &bb[nt >> 1][(nt & 1) * 2]);
        }

        // ---- epilogue: in-thread reduce, then split-ownership tree ----
        float MX[16], MN[16], S[16], Q[16];
#pragma unroll
        for (int nt = 0; nt < 8; nt++) {
            float a0 = acc[0][nt][0], a2 = acc[0][nt][2], b0 = acc[1][nt][0], b2 = acc[1][nt][2];
            MX[2*nt]   = fmaxf(fmaxf(a0, a2), fmaxf(b0, b2));
            MN[2*nt]   = fminf(fminf(a0, a2), fminf(b0, b2));
            S [2*nt]   = (a0 + a2) + (b0 + b2);
            Q [2*nt]   = fmaf(a0,a0, fmaf(a2,a2, fmaf(b0,b0, b2*b2)));
            float a1 = acc[0][nt][1], a3 = acc[0][nt][3], b1 = acc[1][nt][1], b3 = acc[1][nt][3];
            MX[2*nt+1] = fmaxf(fmaxf(a1, a3), fmaxf(b1, b3));
            MN[2*nt+1] = fminf(fminf(a1, a3), fminf(b1, b3));
            S [2*nt+1] = (a1 + a3) + (b1 + b3);
            Q [2*nt+1] = fmaf(a1,a1, fmaf(a3,a3, fmaf(b1,b1, b3*b3)));
        }
#pragma unroll
        for (int st = 0; st < 3; st++) {
            int d   = 4 << st;
            int len = 8 >> st;
            bool up = (lane & d) != 0;
#pragma unroll
            for (int tt = 0; tt < 8; tt++) {
                if (tt >= len) break;
                float sx_, rx, sn_, rn, ss_, rs, sq_, rq;
                sx_ = up ? MX[tt] : MX[tt+len]; rx = __shfl_xor_sync(0xffffffffu, sx_, d);
                MX[tt] = up ? fmaxf(MX[tt+len], rx) : fmaxf(MX[tt], rx);
                sn_ = up ? MN[tt] : MN[tt+len]; rn = __shfl_xor_sync(0xffffffffu, sn_, d);
                MN[tt] = up ? fminf(MN[tt+len], rn) : fminf(MN[tt], rn);
                ss_ = up ? S[tt] : S[tt+len];   rs = __shfl_xor_sync(0xffffffffu, ss_, d);
                S[tt]  = (up ? S[tt+len] : S[tt]) + rs;
                sq_ = up ? Q[tt] : Q[tt+len];   rq = __shfl_xor_sync(0xffffffffu, sq_, d);
                Q[tt]  = (up ? Q[tt+len] : Q[tt]) + rq;
            }
        }
        int v0 = ((lane >> 2) & 1) * 8 + ((lane >> 3) & 1) * 4 + ((lane >> 4) & 1) * 2;
        int c0 = w_c*64 + (v0 >> 1) * 8 + 2*(lane & 3);
        int bnq = bn0 + g*4 + w_r;
        *(float2*)&g_mx[(size_t)bnq*C2_ + c0] = make_float2(MX[0], MX[1]);
        *(float2*)&g_mn[(size_t)bnq*C2_ + c0] = make_float2(MN[0], MN[1]);
        atomicAdd(&ssum[c0],   S[0]);
        atomicAdd(&ssum[c0+1], S[1]);
        atomicAdd(&ssq [c0],   Q[0]);
        atomicAdd(&ssq [c0+1], Q[1]);
    }

    __syncthreads();
    if (t < C2_) {
        atomicAdd(&g_sum2[t], (double)ssum[t]);
        atomicAdd(&g_sq2 [t], (double)ssq [t]);
    }
}

// ---------------- 4) epilogue (BN2 inline per block) ----------------
__global__ void k_out(const float* __restrict__ gamma2, const float* __restrict__ beta2,
                      float* __restrict__ out) {
    __shared__ float a2s[C2_], b2s[C2_];
    int t = threadIdx.x;
    if (t < C2_) {
        double mean = g_sum2[t] * RCNT_;
        double var  = g_sq2[t] * RCNT_ - mean * mean;
        float a = rsqrtf((float)var + EPS_) * gamma2[t];
        a2s[t] = a;
        b2s[t] = beta2[t] - (float)mean * a;
    }
    __syncthreads();
    int base = blockIdx.x * 2048;
#pragma unroll
    for (int j = 0; j < 8; j++) {
        int i = base + j*256 + t;
        int c = i & (C2_ - 1);
        float a = a2s[c], b = b2s[c];
        float x = (a >= 0.f) ? g_mx[i] : g_mn[i];
        out[i] = fmaxf(fmaf(a, x, b), 0.f);
    }
}

// ---------------- launch ----------------
extern "C" void kernel_launch(void* const* d_in, const int* in_sizes, int n_in,
                              void* d_out, int out_size) {
    const float* pos    = (const float*)d_in[0];
    const float* feat   = (const float*)d_in[1];
    const float* W1     = (const float*)d_in[2];
    const float* gamma1 = (const float*)d_in[3];
    const float* beta1  = (const float*)d_in[4];
    const float* W2     = (const float*)d_in[5];
    const float* gamma2 = (const float*)d_in[6];
    const float* beta2  = (const float*)d_in[7];
    float* out = (float*)d_out;

    cudaFuncSetAttribute(k_gemm2t, cudaFuncAttributeMaxDynamicSharedMemorySize, G2T_SMEM);

    k_init      <<<32, 256>>>(W2);
    k_f1        <<<BN_/32, 256>>>(feat, W1);
    k_ballstats <<<B_*(N_/32), 256>>>(pos, W1);
    k_gemm2t    <<<BN_/8, 256, G2T_SMEM>>>(pos, W1, gamma1, beta1);
    k_out       <<<BN_*C2_/2048, 256>>>(gamma2, beta2, out + BN_*3);
    cudaMemcpyAsync(out, pos, (size_t)BN_*3*sizeof(float),
                    cudaMemcpyDeviceToDevice);
}

// round 10
// speedup vs baseline: 3.0912x; 1.1863x over previous
#include <cuda_runtime.h>
#include <cuda_fp16.h>
#include <cstdint>

#define B_   8
#define N_   2048
#define K_   32
#define D_   64
#define C1_  64
#define C2_  128
#define BN_  (B_*N_)
#define R2_  0.0225f
#define EPS_ 1e-5f
#define RCNT_ (1.0/524288.0)   /* exact: 2^-19 */

typedef unsigned long long ull;

// ---------------- helpers ----------------
__device__ __forceinline__ uint32_t smem_u32(const void* p) {
    uint32_t a;
    asm("{ .reg .u64 t; cvta.to.shared.u64 t, %1; cvt.u32.u64 %0, t; }" : "=r"(a) : "l"(p));
    return a;
}
#define SW128(off) ((off) ^ (((off) >> 3) & 0x70))

__device__ __forceinline__ void mma_f16(float* d, const uint32_t* a, const uint32_t* b) {
    asm volatile(
        "mma.sync.aligned.m16n8k16.row.col.f32.f16.f16.f32 "
        "{%0,%1,%2,%3}, {%4,%5,%6,%7}, {%8,%9}, {%0,%1,%2,%3};"
        : "+f"(d[0]), "+f"(d[1]), "+f"(d[2]), "+f"(d[3])
        : "r"(a[0]), "r"(a[1]), "r"(a[2]), "r"(a[3]), "r"(b[0]), "r"(b[1]));
}
__device__ __forceinline__ void ldsm_x4(uint32_t* r, uint32_t addr) {
    asm volatile("ldmatrix.sync.aligned.m8n8.x4.shared.b16 {%0,%1,%2,%3}, [%4];"
        : "=r"(r[0]), "=r"(r[1]), "=r"(r[2]), "=r"(r[3]) : "r"(addr));
}

// packed fp32x2 helpers (k_f1)
__device__ __forceinline__ void fma2(ull& d, ull a, ull b) {
    asm("fma.rn.f32x2 %0, %1, %2, %0;" : "+l"(d) : "l"(a), "l"(b));
}
__device__ __forceinline__ ull pack2(float x, float y) {
    ull r; asm("mov.b64 %0, {%1, %2};" : "=l"(r) : "f"(x), "f"(y)); return r;
}
__device__ __forceinline__ void unpack2(float& x, float& y, ull v) {
    asm("mov.b64 {%0, %1}, %2;" : "=f"(x), "=f"(y) : "l"(v));
}

// ---------------- device scratch ----------------
__device__ int    g_idx[BN_*K_];
__device__ float  g_F1[BN_*C1_];
__device__ double g_sum1[C1_], g_sq1[C1_];
__device__ double g_sum2[C2_], g_sq2[C2_];
__device__ float  g_mx[BN_*C2_];
__device__ float  g_mn[BN_*C2_];
__device__ __half g_W2t[C2_*D_];   // [n][k] transposed W2, fp16

// ---------------- 0) init ----------------
__global__ void k_init(const float* __restrict__ W2) {
    int t = threadIdx.x;
    if (blockIdx.x == 0) {
        if (t < C1_) { g_sum1[t] = 0.0; g_sq1[t] = 0.0; }
        if (t < C2_) { g_sum2[t] = 0.0; g_sq2[t] = 0.0; }
    }
    int i = blockIdx.x * 256 + t;
    if (i < D_*C2_) {
        int k = i >> 7, n = i & 127;
        g_W2t[n*D_ + k] = __float2half_rn(W2[i]);
    }
}

// ---------------- 1) F1 = feature @ W1[3:,:] ----------------
__global__ void k_f1(const float* __restrict__ feat, const float* __restrict__ W1) {
    __shared__ float sW[D_][C1_];
    __shared__ float sIn[32][D_+1];
    int row0 = blockIdx.x * 32;
    for (int i = threadIdx.x; i < D_*C1_; i += 256)
        sW[i / C1_][i % C1_] = W1[(3 + i / C1_) * C1_ + (i % C1_)];
    for (int i = threadIdx.x; i < 32*D_; i += 256)
        sIn[i / D_][i % D_] = feat[(size_t)(row0 + i / D_) * D_ + (i % D_)];
    __syncthreads();
    int k = threadIdx.x >> 3, c0 = (threadIdx.x & 7) << 3;
    ull acc[4];
#pragma unroll
    for (int j = 0; j < 4; j++) acc[j] = 0ull;
    for (int i = 0; i < D_; i++) {
        ull a = pack2(sIn[k][i], sIn[k][i]);
        const ull* wr = (const ull*)&sW[i][c0];
#pragma unroll
        for (int j = 0; j < 4; j++) fma2(acc[j], a, wr[j]);
    }
    float* o = &g_F1[(size_t)(row0 + k) * C1_ + c0];
#pragma unroll
    for (int j = 0; j < 4; j++) { float x, y; unpack2(x, y, acc[j]); o[2*j] = x; o[2*j+1] = y; }
}

// ---------------- 2) fused ball query + h1 stats: 16 queries/block, 2/warp ----------------
__global__ void k_ballstats(const float* __restrict__ pos, const float* __restrict__ W1) {
    __shared__ float sx[N_], sy[N_], sz[N_], sn[N_];
    __shared__ int   sbuf[8][2][K_];
    __shared__ float ssum[C1_], ssq[C1_];
    int t = threadIdx.x;
    int b    = blockIdx.x >> 7;            // 128 blocks per batch
    int qblk = blockIdx.x & 127;           // 16 queries per block
    const float* p = pos + (size_t)b * N_ * 3;
    for (int i = t; i < N_; i += 256) {
        float x = p[3*i], y = p[3*i+1], z = p[3*i+2];
        sx[i] = x; sy[i] = y; sz[i] = z; sn[i] = x*x + y*y + z*z;
    }
    if (t < C1_) { ssum[t] = 0.f; ssq[t] = 0.f; }
    __syncthreads();

    int w = t >> 5, lane = t & 31;
    int qbase = qblk * 16 + w * 2;
    float qx0 = sx[qbase+0], qy0 = sy[qbase+0], qz0 = sz[qbase+0], qn0 = sn[qbase+0];
    float qx1 = sx[qbase+1], qy1 = sy[qbase+1], qz1 = sz[qbase+1], qn1 = sn[qbase+1];
    int cnt0 = 0, cnt1 = 0;

    for (int base = 0; base < N_; base += 32) {
        if (cnt0 >= K_ && cnt1 >= K_) break;
        int m = base + lane;
        float cx = sx[m], cy = sy[m], cz = sz[m], cn = sn[m];
#define BALLQ(ii) \
        if (cnt##ii < K_) { \
            float dot = qx##ii*cx + qy##ii*cy + qz##ii*cz; \
            float sq  = qn##ii + cn - 2.0f*dot; \
            bool in   = (sq <= R2_); \
            unsigned msk = __ballot_sync(0xffffffffu, in); \
            if (in) { \
                int ps = cnt##ii + __popc(msk & ((1u << lane) - 1u)); \
                if (ps < K_) sbuf[w][ii][ps] = m; \
            } \
            cnt##ii += __popc(msk); \
        }
        BALLQ(0) BALLQ(1)
#undef BALLQ
    }
    __syncwarp();

    float wx0 = W1[2*lane],       wx1 = W1[2*lane+1];
    float wy0 = W1[C1_+2*lane],   wy1 = W1[C1_+2*lane+1];
    float wz0 = W1[2*C1_+2*lane], wz1 = W1[2*C1_+2*lane+1];
    const float* F1b = g_F1 + (size_t)b * N_ * C1_;

    float s0 = 0.f, s1 = 0.f, acq0 = 0.f, acq1 = 0.f;
    int cnts[2] = {cnt0, cnt1};
#pragma unroll
    for (int qq = 0; qq < 2; qq++) {
        int q = qbase + qq;
        int v = (lane < cnts[qq]) ? sbuf[w][qq][lane] : sbuf[w][qq][0];
        g_idx[(b*N_ + q)*K_ + lane] = v;
        float qx = sx[q], qy = sy[q], qz = sz[q];
#pragma unroll 8
        for (int k = 0; k < K_; k++) {
            int m = __shfl_sync(0xffffffffu, v, k);
            float dx = sx[m] - qx, dy = sy[m] - qy, dz = sz[m] - qz;
            float2 f = *(const float2*)(F1b + (size_t)m * C1_ + 2*lane);
            float v0 = f.x + dx*wx0 + dy*wy0 + dz*wz0;
            float v1 = f.y + dx*wx1 + dy*wy1 + dz*wz1;
            s0 += v0; acq0 = fmaf(v0, v0, acq0);
            s1 += v1; acq1 = fmaf(v1, v1, acq1);
        }
    }
    atomicAdd(&ssum[2*lane],   s0);
    atomicAdd(&ssum[2*lane+1], s1);
    atomicAdd(&ssq [2*lane],   acq0);
    atomicAdd(&ssq [2*lane+1], acq1);
    __syncthreads();
    if (t < C1_) {
        atomicAdd(&g_sum1[t], (double)ssum[t]);
        atomicAdd(&g_sq1 [t], (double)ssq [t]);
    }
}

// ---------------- 3) HMMA gemm2: col-split tiles for 3 blocks/SM ----------------
#define A_ROWS   256
#define OFF_B    32768
#define OFF_EX   49152
#define G2T_SMEM (OFF_EX + 2048*4 + 1024)

extern __shared__ char dynraw[];
__global__ __launch_bounds__(256, 3)
void k_gemm2t(const float* __restrict__ pos, const float* __restrict__ W1,
              const float* __restrict__ gamma1, const float* __restrict__ beta1) {
    uint32_t rawb  = smem_u32(dynraw);
    uint32_t abase = (rawb + 1023) & ~1023u;
    char*    al    = dynraw + (abase - rawb);
    float*   ex    = (float*)(al + OFF_EX);

    float* sWx  = ex;          // 192
    float* sA1  = ex + 192;    // 64
    float* sB1  = ex + 256;    // 64
    float* sDx  = ex + 320;    // 256
    float* sDy  = ex + 576;    // 256
    float* sDz  = ex + 832;    // 256
    int*   sM   = (int*)(ex + 1088);  // 256
    float* ssum = ex + 1344;   // 128
    float* ssq  = ex + 1472;   // 128

    int t   = threadIdx.x;
    int wid = t >> 5, lane = t & 31;
    int bn0 = blockIdx.x * 8;

    if (t < 3*C1_) sWx[t] = W1[t];
    if (t < C1_) {
        double mean = g_sum1[t] * RCNT_;
        double var  = g_sq1[t] * RCNT_ - mean * mean;
        float a = rsqrtf((float)var + EPS_) * gamma1[t];
        sA1[t] = a;
        sB1[t] = beta1[t] - (float)mean * a;
    }
    if (t < C2_)   { ssum[t] = 0.f; ssq[t] = 0.f; }
    {
        int r  = t;
        int bn = bn0 + (r >> 5);
        int k  = r & 31;
        int b  = bn >> 11;
        int m  = g_idx[bn*K_ + k];
        sM[r]  = b*N_ + m;
        float cx = pos[bn*3+0], cy = pos[bn*3+1], cz = pos[bn*3+2];
        const float* pm = pos + (size_t)(b*N_ + m) * 3;
        sDx[r] = pm[0]-cx; sDy[r] = pm[1]-cy; sDz[r] = pm[2]-cz;
    }

    // B tile: fp16, SW128
    for (int i = t; i < 128*16; i += 256) {
        int n = i >> 4, k8 = i & 15;
        uint32_t off = SW128((uint32_t)(n*128 + k8*8));
        *(ull*)(al + OFF_B + off) = ((const ull*)g_W2t)[i];
    }
    __syncthreads();

    // A tile build: fixed column-pair per thread; single swizzled store per row.
    {
        int c = lane * 2;
        float w1x0 = sWx[c],        w1x1 = sWx[c+1];
        float w1y0 = sWx[C1_+c],    w1y1 = sWx[C1_+c+1];
        float w1z0 = sWx[2*C1_+c],  w1z1 = sWx[2*C1_+c+1];
        float a10  = sA1[c],        a11  = sA1[c+1];
        float b10  = sB1[c],        b11  = sB1[c+1];
#pragma unroll 4
        for (int j = 0; j < 32; j++) {
            int r = wid + j*8;
            float dx = sDx[r], dy = sDy[r], dz = sDz[r];
            float2 f = *(const float2*)(g_F1 + (size_t)sM[r]*C1_ + c);
            float v0 = f.x + dx*w1x0 + dy*w1y0 + dz*w1z0;
            float v1 = f.y + dx*w1x1 + dy*w1y1 + dz*w1z1;
            v0 = fmaxf(fmaf(v0, a10, b10), 0.f);
            v1 = fmaxf(fmaf(v1, a11, b11), 0.f);
            __half h0 = __float2half_rn(v0);
            __half h1 = __float2half_rn(v1);
            uint32_t hp = (uint32_t)*(const uint16_t*)&h0 | ((uint32_t)*(const uint16_t*)&h1 << 16);
            *(uint32_t*)(al + SW128((uint32_t)(r*128 + 4*lane))) = hp;
        }
    }
    __syncthreads();

    // warp tiling: 4 row-warps x 2 col-warps; each warp does its 64 cols in two
    // 32-col halves sequentially (acc = 32 regs -> 3 blocks/SM).
    int w_r = wid & 3, w_c = wid >> 2;
    uint32_t Aa = abase, Bb = abase + OFF_B;

    int kbA = (lane >> 4) * 16;
    int kbB = ((lane >> 3) & 1) * 16;
    int rA  = w_r*32 + (lane & 15);
    int nBl = ((lane >> 4) << 3) + (lane & 7);

#pragma unroll
    for (int g = 0; g < 2; g++) {
#pragma unroll
        for (int h = 0; h < 2; h++) {
            float acc[2][4][4];
#pragma unroll
            for (int mt = 0; mt < 2; mt++)
#pragma unroll
                for (int nt = 0; nt < 4; nt++)
#pragma unroll
                    for (int j = 0; j < 4; j++) acc[mt][nt][j] = 0.f;

#pragma unroll
            for (int ks = 0; ks < 4; ks++) {
                uint32_t ah[2][4], bb[2][4];
#pragma unroll
                for (int mt = 0; mt < 2; mt++)
                    ldsm_x4(ah[mt], Aa + SW128((uint32_t)((g*128 + rA + mt*16)*128 + ks*32 + kbA)));
#pragma unroll
                for (int np = 0; np < 2; np++)
                    ldsm_x4(bb[np], Bb + SW128((uint32_t)((w_c*64 + h*32 + np*16 + nBl)*128 + ks*32 + kbB)));
#pragma unroll
                for (int mt = 0; mt < 2; mt++)
#pragma unroll
                    for (int nt = 0; nt < 4; nt++)
                        mma_f16(acc[mt][nt], ah[mt], &bb[nt >> 1][(nt & 1) * 2]);
            }

            // ---- epilogue: in-thread reduce, split-ownership tree over 8 vars ----
            float MX[8], MN[8], S[8], Q[8];
#pragma unroll
            for (int nt = 0; nt < 4; nt++) {
                float a0 = acc[0][nt][0], a2 = acc[0][nt][2], b0 = acc[1][nt][0], b2 = acc[1][nt][2];
                MX[2*nt]   = fmaxf(fmaxf(a0, a2), fmaxf(b0, b2));
                MN[2*nt]   = fminf(fminf(a0, a2), fminf(b0, b2));
                S [2*nt]   = (a0 + a2) + (b0 + b2);
                Q [2*nt]   = fmaf(a0,a0, fmaf(a2,a2, fmaf(b0,b0, b2*b2)));
                float a1 = acc[0][nt][1], a3 = acc[0][nt][3], b1 = acc[1][nt][1], b3 = acc[1][nt][3];
                MX[2*nt+1] = fmaxf(fmaxf(a1, a3), fmaxf(b1, b3));
                MN[2*nt+1] = fminf(fminf(a1, a3), fminf(b1, b3));
                S [2*nt+1] = (a1 + a3) + (b1 + b3);
                Q [2*nt+1] = fmaf(a1,a1, fmaf(a3,a3, fmaf(b1,b1, b3*b3)));
            }
#pragma unroll
            for (int st = 0; st < 3; st++) {
                int d   = 4 << st;      // 4, 8, 16
                int len = 4 >> st;      // 4, 2, 1
                bool up = (lane & d) != 0;
#pragma unroll
                for (int tt = 0; tt < 4; tt++) {
                    if (tt >= len) break;
                    float sx_, rx, sn_, rn, ss_, rs, sq_, rq;
                    sx_ = up ? MX[tt] : MX[tt+len]; rx = __shfl_xor_sync(0xffffffffu, sx_, d);
                    MX[tt] = up ? fmaxf(MX[tt+len], rx) : fmaxf(MX[tt], rx);
                    sn_ = up ? MN[tt] : MN[tt+len]; rn = __shfl_xor_sync(0xffffffffu, sn_, d);
                    MN[tt] = up ? fminf(MN[tt+len], rn) : fminf(MN[tt], rn);
                    ss_ = up ? S[tt] : S[tt+len];   rs = __shfl_xor_sync(0xffffffffu, ss_, d);
                    S[tt]  = (up ? S[tt+len] : S[tt]) + rs;
                    sq_ = up ? Q[tt] : Q[tt+len];   rq = __shfl_xor_sync(0xffffffffu, sq_, d);
                    Q[tt]  = (up ? Q[tt+len] : Q[tt]) + rq;
                }
            }
            int v0 = ((lane >> 2) & 1) * 4 + ((lane >> 3) & 1) * 2 + ((lane >> 4) & 1);
            int c0 = w_c*64 + h*32 + (v0 >> 1) * 8 + 2*(lane & 3) + (v0 & 1);
            int bnq = bn0 + g*4 + w_r;
            g_mx[(size_t)bnq*C2_ + c0] = MX[0];
            g_mn[(size_t)bnq*C2_ + c0] = MN[0];
            atomicAdd(&ssum[c0], S[0]);
            atomicAdd(&ssq [c0], Q[0]);
        }
    }

    __syncthreads();
    if (t < C2_) {
        atomicAdd(&g_sum2[t], (double)ssum[t]);
        atomicAdd(&g_sq2 [t], (double)ssq [t]);
    }
}

// ---------------- 4) epilogue (BN2 inline per block) ----------------
__global__ void k_out(const float* __restrict__ gamma2, const float* __restrict__ beta2,
                      float* __restrict__ out) {
    __shared__ float a2s[C2_], b2s[C2_];
    int t = threadIdx.x;
    if (t < C2_) {
        double mean = g_sum2[t] * RCNT_;
        double var  = g_sq2[t] * RCNT_ - mean * mean;
        float a = rsqrtf((float)var + EPS_) * gamma2[t];
        a2s[t] = a;
        b2s[t] = beta2[t] - (float)mean * a;
    }
    __syncthreads();
    int base = blockIdx.x * 2048;
#pragma unroll
    for (int j = 0; j < 8; j++) {
        int i = base + j*256 + t;
        int c = i & (C2_ - 1);
        float a = a2s[c], b = b2s[c];
        float x = (a >= 0.f) ? g_mx[i] : g_mn[i];
        out[i] = fmaxf(fmaf(a, x, b), 0.f);
    }
}

// ---------------- launch ----------------
extern "C" void kernel_launch(void* const* d_in, const int* in_sizes, int n_in,
                              void* d_out, int out_size) {
    const float* pos    = (const float*)d_in[0];
    const float* feat   = (const float*)d_in[1];
    const float* W1     = (const float*)d_in[2];
    const float* gamma1 = (const float*)d_in[3];
    const float* beta1  = (const float*)d_in[4];
    const float* W2     = (const float*)d_in[5];
    const float* gamma2 = (const float*)d_in[6];
    const float* beta2  = (const float*)d_in[7];
    float* out = (float*)d_out;

    cudaFuncSetAttribute(k_gemm2t, cudaFuncAttributeMaxDynamicSharedMemorySize, G2T_SMEM);

    k_init      <<<32, 256>>>(W2);
    k_f1        <<<BN_/32, 256>>>(feat, W1);
    k_ballstats <<<B_*(N_/16), 256>>>(pos, W1);
    k_gemm2t    <<<BN_/8, 256, G2T_SMEM>>>(pos, W1, gamma1, beta1);
    k_out       <<<BN_*C2_/2048, 256>>>(gamma2, beta2, out + BN_*3);
    cudaMemcpyAsync(out, pos, (size_t)BN_*3*sizeof(float),
                    cudaMemcpyDeviceToDevice);
}